// round 1
// baseline (speedup 1.0000x reference)
#include <cuda_runtime.h>

// Problem constants
#define Bn 2
#define Sn 2048
#define Dn 1024
#define Hn 16
#define DKn 64
#define MAXSEQ 2048
#define MROWS (Bn * Sn)            // 4096
#define OUT_ELEMS (MROWS * Dn)     // 4,194,304
#define ATTN_ELEMS (Bn * Hn * Sn * Sn)  // 134,217,728

// Scratch (device globals: allocation-free)
__device__ float g_Q[Bn * Sn * Dn];
__device__ float g_K[Bn * Sn * Dn];
__device__ float g_V[Bn * Sn * Dn];
__device__ float g_CTX[Bn * Sn * Dn];
__device__ float g_RINV[Bn * Hn * Sn];

// ---------------------------------------------------------------------------
// GEMM: C[m,n] = sum_k A[m,k] * W[n,k]  (+bias)
// mode 0/1/2: A = Aext (query/key/value), C = g_Q/g_K/g_V with head-permute
//             output layout [b,h,s,dk]
// mode 3:     A = g_CTX ([b,s,d] row-major), C = Cext (d_out), + bias
// M=4096, N=1024, K=1024 fixed.
// ---------------------------------------------------------------------------
__global__ __launch_bounds__(256)
void gemm_kernel(const float* __restrict__ Aext,
                 const float* __restrict__ W,
                 const float* __restrict__ bias,
                 float* __restrict__ Cext,
                 int mode)
{
    __shared__ float As[64][17];
    __shared__ float Ws[64][17];

    const float* A = (mode == 3) ? g_CTX : Aext;
    float* C = (mode == 0) ? g_Q : (mode == 1) ? g_K : (mode == 2) ? g_V : Cext;

    const int tx = threadIdx.x, ty = threadIdx.y;
    const int tid = ty * 16 + tx;
    const int m0 = blockIdx.y * 64;
    const int n0 = blockIdx.x * 64;
    const int K = 1024;

    float acc[4][4] = {};

    for (int k0 = 0; k0 < K; k0 += 16) {
#pragma unroll
        for (int r = 0; r < 4; r++) {
            int e = tid + r * 256;
            int row = e >> 4, col = e & 15;
            As[row][col] = A[(size_t)(m0 + row) * K + k0 + col];
            Ws[row][col] = W[(size_t)(n0 + row) * K + k0 + col];
        }
        __syncthreads();
#pragma unroll
        for (int kk = 0; kk < 16; kk++) {
            float a[4], b[4];
#pragma unroll
            for (int i = 0; i < 4; i++) a[i] = As[ty * 4 + i][kk];
#pragma unroll
            for (int j = 0; j < 4; j++) b[j] = Ws[tx * 4 + j][kk];
#pragma unroll
            for (int i = 0; i < 4; i++)
#pragma unroll
                for (int j = 0; j < 4; j++)
                    acc[i][j] += a[i] * b[j];
        }
        __syncthreads();
    }

#pragma unroll
    for (int i = 0; i < 4; i++) {
        int m = m0 + ty * 4 + i;
#pragma unroll
        for (int j = 0; j < 4; j++) {
            int n = n0 + tx * 4 + j;
            float v = acc[i][j];
            if (mode == 3) {
                v += bias[n];
                C[(size_t)m * 1024 + n] = v;
            } else {
                int b_ = m >> 11;          // m / Sn
                int s_ = m & (Sn - 1);
                int h_ = n >> 6;           // n / DKn
                int dk = n & (DKn - 1);
                C[(((size_t)(b_ * Hn + h_) * Sn) + s_) * DKn + dk] = v;
            }
        }
    }
}

// ---------------------------------------------------------------------------
// Attention: one block per (b*h, 64-query tile).
// Single pass over K/V: p_unnorm = exp(qk/8 + bias) written to attn gmem &
// smem; ctx accumulated in registers; row-sums reduced at the end; ctx scaled
// by 1/rowsum; 1/rowsum stored for the attn fixup kernel.
// Dynamic smem: Qs[64*65] | KPs[64*65] | Vs[64*64]  = 49,664 bytes
// ---------------------------------------------------------------------------
#define ATTN_SMEM_BYTES ((64 * 65 + 64 * 65 + 64 * 64) * 4)

extern __shared__ float sh[];

__global__ __launch_bounds__(256)
void attn_kernel(const float* __restrict__ bias_table,
                 float* __restrict__ attn_out)
{
    float* Qs  = sh;               // 64 x 65
    float* KPs = sh + 64 * 65;     // 64 x 65 (K tile, then reused for P)
    float* Vs  = sh + 2 * 64 * 65; // 64 x 64

    __shared__ float bias_s[128];
    __shared__ float red[64 * 16];
    __shared__ float rinv[64];

    const int tx = threadIdx.x, ty = threadIdx.y;
    const int tid = ty * 16 + tx;
    const int qt = blockIdx.x;
    const int bh = blockIdx.y;
    const int b_ = bh >> 4;
    const int h_ = bh & 15;
    const int q0 = qt * 64;

    const float* Qb = g_Q + (size_t)bh * Sn * DKn;
    const float* Kb = g_K + (size_t)bh * Sn * DKn;
    const float* Vb = g_V + (size_t)bh * Sn * DKn;

    // Load Q tile (64 x 64)
#pragma unroll
    for (int r = 0; r < 16; r++) {
        int e = tid + r * 256;
        int row = e >> 6, col = e & 63;
        Qs[row * 65 + col] = Qb[(size_t)(q0 + row) * DKn + col];
    }

    float ctx[4][4] = {};
    float psum[4] = {};

    for (int kt = 0; kt < 32; kt++) {
        const int k0 = kt * 64;
        __syncthreads();  // previous iter readers done before overwriting tiles

        // Load K tile and V tile
#pragma unroll
        for (int r = 0; r < 16; r++) {
            int e = tid + r * 256;
            int row = e >> 6, col = e & 63;
            KPs[row * 65 + col] = Kb[(size_t)(k0 + row) * DKn + col];
            Vs[row * 64 + col]  = Vb[(size_t)(k0 + row) * DKn + col];
        }
        // Bias slice: rel = (q0 - k0 + MAXSEQ-1) + (qi - kj), qi-kj in [-63,63]
        if (tid < 127) {
            int rel0 = q0 - k0 + (MAXSEQ - 1) - 63;
            bias_s[tid] = bias_table[(size_t)(rel0 + tid) * Hn + h_];
        }
        __syncthreads();

        // Scores: s[q][k] = sum_dk Q[q][dk] * K[k][dk]
        float acc[4][4] = {};
#pragma unroll 16
        for (int kk = 0; kk < 64; kk++) {
            float a[4], bb[4];
#pragma unroll
            for (int i = 0; i < 4; i++) a[i] = Qs[(ty * 4 + i) * 65 + kk];
#pragma unroll
            for (int j = 0; j < 4; j++) bb[j] = KPs[(tx * 4 + j) * 65 + kk];
#pragma unroll
            for (int i = 0; i < 4; i++)
#pragma unroll
                for (int j = 0; j < 4; j++)
                    acc[i][j] += a[i] * bb[j];
        }
        __syncthreads();  // all threads done reading K from KPs

        // exp (no max-subtraction: |s| <= ~3 by construction), write p
#pragma unroll
        for (int i = 0; i < 4; i++) {
            int qi = ty * 4 + i;
            float4 pv;
            float* pp = &pv.x;
#pragma unroll
            for (int j = 0; j < 4; j++) {
                int kj = tx * 4 + j;
                float s = acc[i][j] * 0.125f + bias_s[qi - kj + 63];
                float e = __expf(s);
                psum[i] += e;
                KPs[qi * 65 + kj] = e;
                pp[j] = e;
            }
            if (attn_out) {
                size_t base = ((size_t)(bh * Sn + q0 + qi)) * Sn + k0 + tx * 4;
                *reinterpret_cast<float4*>(attn_out + base) = pv;
            }
        }
        __syncthreads();

        // ctx[q][dk] += P[q][k] * V[k][dk]
#pragma unroll 16
        for (int kk = 0; kk < 64; kk++) {
            float a[4];
#pragma unroll
            for (int i = 0; i < 4; i++) a[i] = KPs[(ty * 4 + i) * 65 + kk];
            float4 bv = *reinterpret_cast<const float4*>(&Vs[kk * 64 + tx * 4]);
            const float bj[4] = {bv.x, bv.y, bv.z, bv.w};
#pragma unroll
            for (int i = 0; i < 4; i++)
#pragma unroll
                for (int j = 0; j < 4; j++)
                    ctx[i][j] += a[i] * bj[j];
        }
    }
    __syncthreads();

    // Row-sum reduction across the 16 tx lanes
#pragma unroll
    for (int i = 0; i < 4; i++) red[(ty * 4 + i) * 16 + tx] = psum[i];
    __syncthreads();
    if (tid < 64) {
        float s = 0.f;
#pragma unroll
        for (int t = 0; t < 16; t++) s += red[tid * 16 + t];
        float r = 1.0f / s;
        rinv[tid] = r;
        g_RINV[bh * Sn + q0 + tid] = r;
    }
    __syncthreads();

    // Scale ctx and write in [b, s, d] layout for the output projection
#pragma unroll
    for (int i = 0; i < 4; i++) {
        int qi = ty * 4 + i;
        float r = rinv[qi];
        float4 cv;
        cv.x = ctx[i][0] * r;
        cv.y = ctx[i][1] * r;
        cv.z = ctx[i][2] * r;
        cv.w = ctx[i][3] * r;
        size_t o = ((size_t)(b_ * Sn + q0 + qi)) * Dn + h_ * DKn + tx * 4;
        *reinterpret_cast<float4*>(g_CTX + o) = cv;
    }
}

// ---------------------------------------------------------------------------
// Fixup: attn[i] *= 1/rowsum  (float4-vectorized; row = element_index / Sn)
// ---------------------------------------------------------------------------
__global__ __launch_bounds__(256)
void fixup_kernel(float* __restrict__ attn)
{
    size_t i4 = (size_t)blockIdx.x * blockDim.x + threadIdx.x;  // float4 index
    // ATTN_ELEMS/4 = 33,554,432; grid sized to exactly cover
    int row = (int)(i4 >> 9);  // (i4*4) / 2048
    float r = g_RINV[row];
    float4 v = reinterpret_cast<float4*>(attn)[i4];
    v.x *= r; v.y *= r; v.z *= r; v.w *= r;
    reinterpret_cast<float4*>(attn)[i4] = v;
}

// ---------------------------------------------------------------------------
extern "C" void kernel_launch(void* const* d_in, const int* in_sizes, int n_in,
                              void* d_out, int out_size)
{
    const float* query      = (const float*)d_in[0];
    const float* key        = (const float*)d_in[1];
    const float* value      = (const float*)d_in[2];
    const float* Wq         = (const float*)d_in[3];
    const float* Wk         = (const float*)d_in[4];
    const float* Wv         = (const float*)d_in[5];
    const float* Wo         = (const float*)d_in[6];
    const float* bo         = (const float*)d_in[7];
    const float* bias_table = (const float*)d_in[8];

    float* out = (float*)d_out;
    const bool has_attn = out_size >= (OUT_ELEMS + ATTN_ELEMS);
    float* attn = has_attn ? out + OUT_ELEMS : nullptr;

    cudaFuncSetAttribute(attn_kernel,
                         cudaFuncAttributeMaxDynamicSharedMemorySize,
                         ATTN_SMEM_BYTES);

    dim3 blk(16, 16);
    dim3 gproj(16, 64);   // N/64, M/64
    gemm_kernel<<<gproj, blk>>>(query, Wq, nullptr, nullptr, 0);
    gemm_kernel<<<gproj, blk>>>(key,   Wk, nullptr, nullptr, 1);
    gemm_kernel<<<gproj, blk>>>(value, Wv, nullptr, nullptr, 2);

    dim3 gattn(Sn / 64, Bn * Hn);  // 32 x 32
    attn_kernel<<<gattn, blk, ATTN_SMEM_BYTES>>>(bias_table, attn);

    gemm_kernel<<<gproj, blk>>>(nullptr, Wo, bo, out, 3);

    if (has_attn) {
        fixup_kernel<<<ATTN_ELEMS / 4 / 256, 256>>>(attn);  // 131072 blocks
    }
}

// round 2
// speedup vs baseline: 2.0457x; 2.0457x over previous
#include <cuda_runtime.h>

#define Bn 2
#define Sn 2048
#define Dn 1024
#define Hn 16
#define DKn 64
#define MAXSEQ 2048
#define MROWS (Bn * Sn)
#define OUT_ELEMS (MROWS * Dn)
#define ATTN_ELEMS ((long long)Bn * Hn * Sn * Sn)

// Scratch (device globals: allocation-free)
__device__ float g_Q[Bn * Sn * Dn];
__device__ float g_K[Bn * Sn * Dn];
__device__ float g_V[Bn * Sn * Dn];
__device__ float g_CTX[Bn * Sn * Dn];

// ---------------------------------------------------------------------------
// tf32 helpers
// ---------------------------------------------------------------------------
__device__ __forceinline__ unsigned f2tf(float x) {
    unsigned u;
    asm("cvt.rna.tf32.f32 %0, %1;" : "=r"(u) : "f"(x));
    return u;
}

__device__ __forceinline__ void mma_tf32(float c[4], const unsigned a[4],
                                         const unsigned b[2]) {
    asm volatile(
        "mma.sync.aligned.m16n8k8.row.col.f32.tf32.tf32.f32 "
        "{%0,%1,%2,%3}, {%4,%5,%6,%7}, {%8,%9}, {%0,%1,%2,%3};"
        : "+f"(c[0]), "+f"(c[1]), "+f"(c[2]), "+f"(c[3])
        : "r"(a[0]), "r"(a[1]), "r"(a[2]), "r"(a[3]), "r"(b[0]), "r"(b[1]));
}

// ---------------------------------------------------------------------------
// Projection GEMM (tf32 MMA): C[m,n] = sum_k A[m,k] * W[n,k] (+bias)
// M=4096, N=1024, K=1024. Block tile 128x64, BK=32, 8 warps (4m x 2n),
// warp tile 32x32 (2x4 m16n8k8 frags).
// mode 0/1/2: C = g_Q/g_K/g_V in [b,h,s,dk]; mode 3: A=g_CTX, C=d_out (+bias)
// ---------------------------------------------------------------------------
#define GBM 128
#define GBN 64
#define GBK 32
#define GPAD 36

__global__ __launch_bounds__(256)
void gemm_tc(const float* __restrict__ Aext, const float* __restrict__ W,
             const float* __restrict__ bias, float* __restrict__ Cext, int mode)
{
    __shared__ unsigned As[GBM * GPAD];
    __shared__ unsigned Ws[GBN * GPAD];

    const float* A = (mode == 3) ? g_CTX : Aext;
    float* C = (mode == 0) ? g_Q : (mode == 1) ? g_K : (mode == 2) ? g_V : Cext;

    const int tid = threadIdx.x;
    const int w = tid >> 5, lane = tid & 31, g = lane >> 2, qr = lane & 3;
    const int wm = w >> 1, wn = w & 1;
    const int m0 = blockIdx.y * GBM, n0 = blockIdx.x * GBN;

    float c[2][4][4] = {};

    for (int k0 = 0; k0 < 1024; k0 += GBK) {
#pragma unroll
        for (int it = 0; it < 4; it++) {
            int idx = tid + it * 256;            // 0..1023 float4 units
            int row = idx >> 3, c4 = idx & 7;
            float4 v = *(const float4*)&A[(size_t)(m0 + row) * 1024 + k0 + c4 * 4];
            unsigned* d = &As[row * GPAD + c4 * 4];
            d[0] = f2tf(v.x); d[1] = f2tf(v.y); d[2] = f2tf(v.z); d[3] = f2tf(v.w);
        }
#pragma unroll
        for (int it = 0; it < 2; it++) {
            int idx = tid + it * 256;            // 0..511
            int row = idx >> 3, c4 = idx & 7;
            float4 v = *(const float4*)&W[(size_t)(n0 + row) * 1024 + k0 + c4 * 4];
            unsigned* d = &Ws[row * GPAD + c4 * 4];
            d[0] = f2tf(v.x); d[1] = f2tf(v.y); d[2] = f2tf(v.z); d[3] = f2tf(v.w);
        }
        __syncthreads();
#pragma unroll
        for (int kk = 0; kk < GBK; kk += 8) {
            unsigned a[2][4], b[4][2];
#pragma unroll
            for (int mi = 0; mi < 2; mi++) {
                int r = wm * 32 + mi * 16 + g;
                a[mi][0] = As[r * GPAD + kk + qr];
                a[mi][1] = As[(r + 8) * GPAD + kk + qr];
                a[mi][2] = As[r * GPAD + kk + qr + 4];
                a[mi][3] = As[(r + 8) * GPAD + kk + qr + 4];
            }
#pragma unroll
            for (int ni = 0; ni < 4; ni++) {
                int col = wn * 32 + ni * 8 + g;
                b[ni][0] = Ws[col * GPAD + kk + qr];
                b[ni][1] = Ws[col * GPAD + kk + qr + 4];
            }
#pragma unroll
            for (int mi = 0; mi < 2; mi++)
#pragma unroll
                for (int ni = 0; ni < 4; ni++)
                    mma_tf32(c[mi][ni], a[mi], b[ni]);
        }
        __syncthreads();
    }

    // Epilogue
#pragma unroll
    for (int mi = 0; mi < 2; mi++)
#pragma unroll
        for (int ni = 0; ni < 4; ni++)
#pragma unroll
            for (int half = 0; half < 2; half++) {
                int row = m0 + wm * 32 + mi * 16 + g + half * 8;
                int col = n0 + wn * 32 + ni * 8 + 2 * qr;
                float v0 = c[mi][ni][half * 2 + 0];
                float v1 = c[mi][ni][half * 2 + 1];
                if (mode == 3) {
                    v0 += bias[col];
                    v1 += bias[col + 1];
                    *(float2*)&C[(size_t)row * 1024 + col] = make_float2(v0, v1);
                } else {
                    int b_ = row >> 11, s_ = row & (Sn - 1);
                    int h_ = col >> 6, dk = col & 63;
                    size_t o = (((size_t)(b_ * Hn + h_) * Sn) + s_) * DKn + dk;
                    *(float2*)&C[o] = make_float2(v0, v1);
                }
            }
}

// ---------------------------------------------------------------------------
// Attention (tf32 MMA, two-pass, direct normalized write):
// grid (32 qtiles, 32 bh), 256 threads = 8 warps (2m x 4n).
// Pass A: per 64-key tile: S=QK^T (mma), p=exp(s/8+bias) -> Ps (tf32),
//         psum in regs, ctx += P@V (mma). Then rinv = 1/rowsum; write
//         scaled ctx to g_CTX.
// Pass B: recompute S, write p*rinv directly to gmem attn.
// ---------------------------------------------------------------------------
#define APAD 68
#define ATTN_SMEM (4 * 64 * APAD * 4)

__global__ __launch_bounds__(256)
void attn_tc(const float* __restrict__ bias_table, float* __restrict__ attn_out)
{
    extern __shared__ unsigned sh[];
    unsigned* Qs = sh;
    unsigned* Ks = sh + 64 * APAD;
    unsigned* Ps = sh + 2 * 64 * APAD;
    unsigned* Vs = sh + 3 * 64 * APAD;
    __shared__ float bias_s[128];
    __shared__ float red[64 * 4];
    __shared__ float rinv_s[64];

    const int tid = threadIdx.x;
    const int w = tid >> 5, lane = tid & 31, g = lane >> 2, qr = lane & 3;
    const int wm = w & 1, wn = w >> 1;      // wm: 2 x 32 q-rows, wn: 4 x 16 cols
    const int qt = blockIdx.x, bh = blockIdx.y;
    const int b_ = bh >> 4, h_ = bh & 15;
    const int q0 = qt * 64;

    const float* Qb = g_Q + (size_t)bh * Sn * DKn;
    const float* Kb = g_K + (size_t)bh * Sn * DKn;
    const float* Vb = g_V + (size_t)bh * Sn * DKn;

    // Load Q tile (64x64) once
#pragma unroll
    for (int it = 0; it < 4; it++) {
        int idx = tid + it * 256;            // 0..1023 float4 units
        int row = idx >> 4, c4 = idx & 15;
        float4 v = *(const float4*)&Qb[(size_t)(q0 + row) * DKn + c4 * 4];
        unsigned* d = &Qs[row * APAD + c4 * 4];
        d[0] = f2tf(v.x); d[1] = f2tf(v.y); d[2] = f2tf(v.z); d[3] = f2tf(v.w);
    }

    float ctx[2][2][4] = {};
    float psum[4] = {};  // rows: q = wm*32 + (i>>1)*16 + g + (i&1)*8

    // ---------------- Pass A ----------------
    for (int kt = 0; kt < 32; kt++) {
        const int k0 = kt * 64;
        __syncthreads();
#pragma unroll
        for (int it = 0; it < 4; it++) {
            int idx = tid + it * 256;
            int row = idx >> 4, c4 = idx & 15;
            float4 kv = *(const float4*)&Kb[(size_t)(k0 + row) * DKn + c4 * 4];
            float4 vv = *(const float4*)&Vb[(size_t)(k0 + row) * DKn + c4 * 4];
            unsigned* dk_ = &Ks[row * APAD + c4 * 4];
            unsigned* dv_ = &Vs[row * APAD + c4 * 4];
            dk_[0] = f2tf(kv.x); dk_[1] = f2tf(kv.y); dk_[2] = f2tf(kv.z); dk_[3] = f2tf(kv.w);
            dv_[0] = f2tf(vv.x); dv_[1] = f2tf(vv.y); dv_[2] = f2tf(vv.z); dv_[3] = f2tf(vv.w);
        }
        if (tid < 127)
            bias_s[tid] = bias_table[(size_t)(q0 - k0 + MAXSEQ - 1 - 63 + tid) * Hn + h_];
        __syncthreads();

        // S = Q K^T
        float sacc[2][2][4] = {};
#pragma unroll
        for (int kk = 0; kk < 64; kk += 8) {
            unsigned a[2][4], b[2][2];
#pragma unroll
            for (int mi = 0; mi < 2; mi++) {
                int r = wm * 32 + mi * 16 + g;
                a[mi][0] = Qs[r * APAD + kk + qr];
                a[mi][1] = Qs[(r + 8) * APAD + kk + qr];
                a[mi][2] = Qs[r * APAD + kk + qr + 4];
                a[mi][3] = Qs[(r + 8) * APAD + kk + qr + 4];
            }
#pragma unroll
            for (int ni = 0; ni < 2; ni++) {
                int col = wn * 16 + ni * 8 + g;
                b[ni][0] = Ks[col * APAD + kk + qr];
                b[ni][1] = Ks[col * APAD + kk + qr + 4];
            }
#pragma unroll
            for (int mi = 0; mi < 2; mi++)
#pragma unroll
                for (int ni = 0; ni < 2; ni++)
                    mma_tf32(sacc[mi][ni], a[mi], b[ni]);
        }

        // exp + bias -> Ps (unnormalized), psum
#pragma unroll
        for (int mi = 0; mi < 2; mi++)
#pragma unroll
            for (int half = 0; half < 2; half++) {
                int qi = wm * 32 + mi * 16 + g + half * 8;
                float rs = 0.f;
#pragma unroll
                for (int ni = 0; ni < 2; ni++) {
                    int kj = wn * 16 + ni * 8 + 2 * qr;
                    float s0 = sacc[mi][ni][half * 2 + 0] * 0.125f + bias_s[qi - kj + 63];
                    float s1 = sacc[mi][ni][half * 2 + 1] * 0.125f + bias_s[qi - kj + 62];
                    float p0 = __expf(s0), p1 = __expf(s1);
                    rs += p0 + p1;
                    Ps[qi * APAD + kj] = f2tf(p0);
                    Ps[qi * APAD + kj + 1] = f2tf(p1);
                }
                psum[mi * 2 + half] += rs;
            }
        __syncthreads();

        // ctx += P @ V
#pragma unroll
        for (int kk = 0; kk < 64; kk += 8) {
            unsigned a[2][4], b[2][2];
#pragma unroll
            for (int mi = 0; mi < 2; mi++) {
                int r = wm * 32 + mi * 16 + g;
                a[mi][0] = Ps[r * APAD + kk + qr];
                a[mi][1] = Ps[(r + 8) * APAD + kk + qr];
                a[mi][2] = Ps[r * APAD + kk + qr + 4];
                a[mi][3] = Ps[(r + 8) * APAD + kk + qr + 4];
            }
#pragma unroll
            for (int ni = 0; ni < 2; ni++) {
                int n = wn * 16 + ni * 8 + g;
                b[ni][0] = Vs[(kk + qr) * APAD + n];
                b[ni][1] = Vs[(kk + qr + 4) * APAD + n];
            }
#pragma unroll
            for (int mi = 0; mi < 2; mi++)
#pragma unroll
                for (int ni = 0; ni < 2; ni++)
                    mma_tf32(ctx[mi][ni], a[mi], b[ni]);
        }
    }

    // Row-sum reduction: quad shuffle, then across the 4 wn warps via smem
#pragma unroll
    for (int i = 0; i < 4; i++) {
        float v = psum[i];
        v += __shfl_xor_sync(0xffffffffu, v, 1);
        v += __shfl_xor_sync(0xffffffffu, v, 2);
        if (qr == 0) {
            int qi = wm * 32 + (i >> 1) * 16 + g + (i & 1) * 8;
            red[qi * 4 + wn] = v;
        }
    }
    __syncthreads();
    if (tid < 64) {
        float s = red[tid * 4] + red[tid * 4 + 1] + red[tid * 4 + 2] + red[tid * 4 + 3];
        rinv_s[tid] = 1.0f / s;
    }
    __syncthreads();

    // Write scaled ctx to g_CTX in [b, s, d] layout
#pragma unroll
    for (int mi = 0; mi < 2; mi++)
#pragma unroll
        for (int ni = 0; ni < 2; ni++)
#pragma unroll
            for (int half = 0; half < 2; half++) {
                int qi = wm * 32 + mi * 16 + g + half * 8;
                float r = rinv_s[qi];
                int dk = wn * 16 + ni * 8 + 2 * qr;
                float2 v = make_float2(ctx[mi][ni][half * 2 + 0] * r,
                                       ctx[mi][ni][half * 2 + 1] * r);
                size_t o = ((size_t)(b_ * Sn + q0 + qi)) * Dn + h_ * DKn + dk;
                *(float2*)&g_CTX[o] = v;
            }

    if (!attn_out) return;

    // ---------------- Pass B: recompute S, write normalized attn ----------
    for (int kt = 0; kt < 32; kt++) {
        const int k0 = kt * 64;
        __syncthreads();
#pragma unroll
        for (int it = 0; it < 4; it++) {
            int idx = tid + it * 256;
            int row = idx >> 4, c4 = idx & 15;
            float4 kv = *(const float4*)&Kb[(size_t)(k0 + row) * DKn + c4 * 4];
            unsigned* dk_ = &Ks[row * APAD + c4 * 4];
            dk_[0] = f2tf(kv.x); dk_[1] = f2tf(kv.y); dk_[2] = f2tf(kv.z); dk_[3] = f2tf(kv.w);
        }
        if (tid < 127)
            bias_s[tid] = bias_table[(size_t)(q0 - k0 + MAXSEQ - 1 - 63 + tid) * Hn + h_];
        __syncthreads();

        float sacc[2][2][4] = {};
#pragma unroll
        for (int kk = 0; kk < 64; kk += 8) {
            unsigned a[2][4], b[2][2];
#pragma unroll
            for (int mi = 0; mi < 2; mi++) {
                int r = wm * 32 + mi * 16 + g;
                a[mi][0] = Qs[r * APAD + kk + qr];
                a[mi][1] = Qs[(r + 8) * APAD + kk + qr];
                a[mi][2] = Qs[r * APAD + kk + qr + 4];
                a[mi][3] = Qs[(r + 8) * APAD + kk + qr + 4];
            }
#pragma unroll
            for (int ni = 0; ni < 2; ni++) {
                int col = wn * 16 + ni * 8 + g;
                b[ni][0] = Ks[col * APAD + kk + qr];
                b[ni][1] = Ks[col * APAD + kk + qr + 4];
            }
#pragma unroll
            for (int mi = 0; mi < 2; mi++)
#pragma unroll
                for (int ni = 0; ni < 2; ni++)
                    mma_tf32(sacc[mi][ni], a[mi], b[ni]);
        }

#pragma unroll
        for (int mi = 0; mi < 2; mi++)
#pragma unroll
            for (int half = 0; half < 2; half++) {
                int qi = wm * 32 + mi * 16 + g + half * 8;
                float r = rinv_s[qi];
#pragma unroll
                for (int ni = 0; ni < 2; ni++) {
                    int kj = wn * 16 + ni * 8 + 2 * qr;
                    float s0 = sacc[mi][ni][half * 2 + 0] * 0.125f + bias_s[qi - kj + 63];
                    float s1 = sacc[mi][ni][half * 2 + 1] * 0.125f + bias_s[qi - kj + 62];
                    float2 pv = make_float2(__expf(s0) * r, __expf(s1) * r);
                    size_t o = ((size_t)(bh * Sn + q0 + qi)) * Sn + k0 + kj;
                    *(float2*)&attn_out[o] = pv;
                }
            }
    }
}

// ---------------------------------------------------------------------------
extern "C" void kernel_launch(void* const* d_in, const int* in_sizes, int n_in,
                              void* d_out, int out_size)
{
    const float* query      = (const float*)d_in[0];
    const float* key        = (const float*)d_in[1];
    const float* value      = (const float*)d_in[2];
    const float* Wq         = (const float*)d_in[3];
    const float* Wk         = (const float*)d_in[4];
    const float* Wv         = (const float*)d_in[5];
    const float* Wo         = (const float*)d_in[6];
    const float* bo         = (const float*)d_in[7];
    const float* bias_table = (const float*)d_in[8];

    float* out = (float*)d_out;
    const bool has_attn = (long long)out_size >= (OUT_ELEMS + ATTN_ELEMS);
    float* attn = has_attn ? out + OUT_ELEMS : nullptr;

    cudaFuncSetAttribute(attn_tc, cudaFuncAttributeMaxDynamicSharedMemorySize,
                         ATTN_SMEM);

    dim3 gproj(1024 / GBN, MROWS / GBM);   // 16 x 32
    gemm_tc<<<gproj, 256>>>(query, Wq, nullptr, nullptr, 0);
    gemm_tc<<<gproj, 256>>>(key,   Wk, nullptr, nullptr, 1);
    gemm_tc<<<gproj, 256>>>(value, Wv, nullptr, nullptr, 2);

    dim3 gattn(Sn / 64, Bn * Hn);          // 32 x 32
    attn_tc<<<gattn, 256, ATTN_SMEM>>>(bias_table, attn);

    gemm_tc<<<gproj, 256>>>(nullptr, Wo, bo, out, 3);
}

// round 3
// speedup vs baseline: 2.3711x; 1.1591x over previous
#include <cuda_runtime.h>

#define Bn 2
#define Sn 2048
#define Dn 1024
#define Hn 16
#define DKn 64
#define MAXSEQ 2048
#define MROWS (Bn * Sn)
#define OUT_ELEMS (MROWS * Dn)
#define ATTN_ELEMS ((long long)Bn * Hn * Sn * Sn)

__device__ float g_Q[Bn * Sn * Dn];
__device__ float g_K[Bn * Sn * Dn];
__device__ float g_V[Bn * Sn * Dn];
__device__ float g_CTX[Bn * Sn * Dn];

__device__ __forceinline__ unsigned f2tf(float x) {
    unsigned u;
    asm("cvt.rna.tf32.f32 %0, %1;" : "=r"(u) : "f"(x));
    return u;
}

__device__ __forceinline__ void mma_tf32(float c[4], const unsigned a[4],
                                         unsigned b0, unsigned b1) {
    asm volatile(
        "mma.sync.aligned.m16n8k8.row.col.f32.tf32.tf32.f32 "
        "{%0,%1,%2,%3}, {%4,%5,%6,%7}, {%8,%9}, {%0,%1,%2,%3};"
        : "+f"(c[0]), "+f"(c[1]), "+f"(c[2]), "+f"(c[3])
        : "r"(a[0]), "r"(a[1]), "r"(a[2]), "r"(a[3]), "r"(b0), "r"(b1));
}

// ---------------------------------------------------------------------------
// Projection GEMM: C[m,n] = sum_k A[m,k]*W[n,k] (+bias). M=4096,N=1024,K=1024
// Block 128x128, 8 warps (2 wm x 4 wn), warp tile 64x32 (4 mi x 4 ni), BK=32.
// ---------------------------------------------------------------------------
#define GPAD 36

__global__ __launch_bounds__(256)
void gemm_tc(const float* __restrict__ Aext, const float* __restrict__ W,
             const float* __restrict__ bias, float* __restrict__ Cext, int mode)
{
    __shared__ unsigned As[128 * GPAD];
    __shared__ unsigned Ws[128 * GPAD];

    const float* A = (mode == 3) ? g_CTX : Aext;
    float* C = (mode == 0) ? g_Q : (mode == 1) ? g_K : (mode == 2) ? g_V : Cext;

    const int tid = threadIdx.x;
    const int w = tid >> 5, lane = tid & 31, g = lane >> 2, qr = lane & 3;
    const int wm = w >> 2, wn = w & 3;
    const int m0 = blockIdx.y * 128, n0 = blockIdx.x * 128;

    float c[4][4][4] = {};

    for (int k0 = 0; k0 < 1024; k0 += 32) {
#pragma unroll
        for (int it = 0; it < 4; it++) {
            int idx = tid + it * 256;          // 1024 float4 units
            int row = idx >> 3, c4 = idx & 7;
            float4 va = *(const float4*)&A[(size_t)(m0 + row) * 1024 + k0 + c4 * 4];
            float4 vw = *(const float4*)&W[(size_t)(n0 + row) * 1024 + k0 + c4 * 4];
            unsigned* da = &As[row * GPAD + c4 * 4];
            unsigned* dw = &Ws[row * GPAD + c4 * 4];
            da[0] = f2tf(va.x); da[1] = f2tf(va.y); da[2] = f2tf(va.z); da[3] = f2tf(va.w);
            dw[0] = f2tf(vw.x); dw[1] = f2tf(vw.y); dw[2] = f2tf(vw.z); dw[3] = f2tf(vw.w);
        }
        __syncthreads();
#pragma unroll
        for (int kk = 0; kk < 32; kk += 8) {
            unsigned a[4][4], b[4][2];
#pragma unroll
            for (int mi = 0; mi < 4; mi++) {
                int r = wm * 64 + mi * 16 + g;
                a[mi][0] = As[r * GPAD + kk + qr];
                a[mi][1] = As[(r + 8) * GPAD + kk + qr];
                a[mi][2] = As[r * GPAD + kk + qr + 4];
                a[mi][3] = As[(r + 8) * GPAD + kk + qr + 4];
            }
#pragma unroll
            for (int ni = 0; ni < 4; ni++) {
                int col = wn * 32 + ni * 8 + g;
                b[ni][0] = Ws[col * GPAD + kk + qr];
                b[ni][1] = Ws[col * GPAD + kk + qr + 4];
            }
#pragma unroll
            for (int mi = 0; mi < 4; mi++)
#pragma unroll
                for (int ni = 0; ni < 4; ni++)
                    mma_tf32(c[mi][ni], a[mi], b[ni][0], b[ni][1]);
        }
        __syncthreads();
    }

#pragma unroll
    for (int mi = 0; mi < 4; mi++)
#pragma unroll
        for (int ni = 0; ni < 4; ni++)
#pragma unroll
            for (int half = 0; half < 2; half++) {
                int row = m0 + wm * 64 + mi * 16 + g + half * 8;
                int col = n0 + wn * 32 + ni * 8 + 2 * qr;
                float v0 = c[mi][ni][half * 2 + 0];
                float v1 = c[mi][ni][half * 2 + 1];
                if (mode == 3) {
                    v0 += bias[col];
                    v1 += bias[col + 1];
                    *(float2*)&C[(size_t)row * 1024 + col] = make_float2(v0, v1);
                } else {
                    int b_ = row >> 11, s_ = row & (Sn - 1);
                    int h_ = col >> 6, dk = col & 63;
                    size_t o = (((size_t)(b_ * Hn + h_) * Sn) + s_) * DKn + dk;
                    *(float2*)&C[o] = make_float2(v0, v1);
                }
            }
}

// ---------------------------------------------------------------------------
// Attention: block = 4 warps x 16 q-rows = 64 q rows; each warp spans the
// full 64-key tile. Q fragments in registers (loaded once, reused by pass A
// and pass B). P converted S-accum -> A-frag via shuffles (no smem P).
// Pass A: ctx + rowsums. Pass B: recompute S, write normalized attn.
// ---------------------------------------------------------------------------
#define KPAD 68
#define VPAD 72

__global__ __launch_bounds__(128)
void attn_tc(const float* __restrict__ bias_table, float* __restrict__ attn_out)
{
    __shared__ unsigned Ks[64 * KPAD];
    __shared__ unsigned Vs[64 * VPAD];
    __shared__ float bias_s[128];

    const int tid = threadIdx.x;
    const int w = tid >> 5, lane = tid & 31, g = lane >> 2, qr = lane & 3;
    const int qt = blockIdx.x, bh = blockIdx.y;
    const int b_ = bh >> 4, h_ = bh & 15;
    const int q0 = qt * 64;
    const int qlo = w * 16 + g;            // local q row (and +8)

    const float* Qb = g_Q + (size_t)bh * Sn * DKn;
    const float* Kb = g_K + (size_t)bh * Sn * DKn;
    const float* Vb = g_V + (size_t)bh * Sn * DKn;

    // Q fragments in registers (16 rows x 64 cols per warp)
    unsigned qa[8][4];
    {
        const float* r0 = Qb + (size_t)(q0 + qlo) * DKn;
        const float* r1 = r0 + 8 * DKn;
#pragma unroll
        for (int kc = 0; kc < 8; kc++) {
            qa[kc][0] = f2tf(r0[kc * 8 + qr]);
            qa[kc][1] = f2tf(r1[kc * 8 + qr]);
            qa[kc][2] = f2tf(r0[kc * 8 + qr + 4]);
            qa[kc][3] = f2tf(r1[kc * 8 + qr + 4]);
        }
    }

    const int src0 = (lane & 28) | (qr >> 1);
    const int src1 = src0 + 2;
    const bool odd = (qr & 1);

    float ctx[8][4] = {};
    float psum0 = 0.f, psum1 = 0.f;

    // ---------------- Pass A ----------------
    for (int kt = 0; kt < 32; kt++) {
        const int k0 = kt * 64;
        __syncthreads();
#pragma unroll
        for (int it = 0; it < 8; it++) {
            int idx = tid + it * 128;        // 1024 float4 units
            int row = idx >> 4, c4 = idx & 15;
            float4 kv = *(const float4*)&Kb[(size_t)(k0 + row) * DKn + c4 * 4];
            float4 vv = *(const float4*)&Vb[(size_t)(k0 + row) * DKn + c4 * 4];
            unsigned* dk_ = &Ks[row * KPAD + c4 * 4];
            unsigned* dv_ = &Vs[row * VPAD + c4 * 4];
            dk_[0] = f2tf(kv.x); dk_[1] = f2tf(kv.y); dk_[2] = f2tf(kv.z); dk_[3] = f2tf(kv.w);
            dv_[0] = f2tf(vv.x); dv_[1] = f2tf(vv.y); dv_[2] = f2tf(vv.z); dv_[3] = f2tf(vv.w);
        }
        if (tid < 127)
            bias_s[tid] = bias_table[(size_t)(q0 - k0 + MAXSEQ - 1 - 63 + tid) * Hn + h_];
        __syncthreads();

        // S = Q K^T  (m16 x n64 per warp)
        float sacc[8][4] = {};
#pragma unroll
        for (int kc = 0; kc < 8; kc++) {
#pragma unroll
            for (int ni = 0; ni < 8; ni++) {
                unsigned b0 = Ks[(ni * 8 + g) * KPAD + kc * 8 + qr];
                unsigned b1 = Ks[(ni * 8 + g) * KPAD + kc * 8 + qr + 4];
                mma_tf32(sacc[ni], qa[kc], b0, b1);
            }
        }

        // exp + bias, rowsums, convert to A-layout via shuffles
        unsigned pA[8][4];
#pragma unroll
        for (int ni = 0; ni < 8; ni++) {
            int idx0 = qlo - (ni * 8 + 2 * qr) + 63;
            float p0 = __expf(sacc[ni][0] * 0.125f + bias_s[idx0]);
            float p1 = __expf(sacc[ni][1] * 0.125f + bias_s[idx0 - 1]);
            float p2 = __expf(sacc[ni][2] * 0.125f + bias_s[idx0 + 8]);
            float p3 = __expf(sacc[ni][3] * 0.125f + bias_s[idx0 + 7]);
            psum0 += p0 + p1;
            psum1 += p2 + p3;
            float u0 = __shfl_sync(0xffffffffu, p0, src0);
            float u1 = __shfl_sync(0xffffffffu, p1, src0);
            pA[ni][0] = f2tf(odd ? u1 : u0);
            float u2 = __shfl_sync(0xffffffffu, p2, src0);
            float u3 = __shfl_sync(0xffffffffu, p3, src0);
            pA[ni][1] = f2tf(odd ? u3 : u2);
            float u4 = __shfl_sync(0xffffffffu, p0, src1);
            float u5 = __shfl_sync(0xffffffffu, p1, src1);
            pA[ni][2] = f2tf(odd ? u5 : u4);
            float u6 = __shfl_sync(0xffffffffu, p2, src1);
            float u7 = __shfl_sync(0xffffffffu, p3, src1);
            pA[ni][3] = f2tf(odd ? u7 : u6);
        }

        // ctx += P @ V
#pragma unroll
        for (int kc = 0; kc < 8; kc++) {
#pragma unroll
            for (int n2 = 0; n2 < 8; n2++) {
                unsigned b0 = Vs[(kc * 8 + qr) * VPAD + n2 * 8 + g];
                unsigned b1 = Vs[(kc * 8 + qr + 4) * VPAD + n2 * 8 + g];
                mma_tf32(ctx[n2], pA[kc], b0, b1);
            }
        }
    }

    // Row sums: reduce across qr lanes (rows fully warp-owned)
    psum0 += __shfl_xor_sync(0xffffffffu, psum0, 1);
    psum0 += __shfl_xor_sync(0xffffffffu, psum0, 2);
    psum1 += __shfl_xor_sync(0xffffffffu, psum1, 1);
    psum1 += __shfl_xor_sync(0xffffffffu, psum1, 2);
    const float rinv0 = 1.0f / psum0;
    const float rinv1 = 1.0f / psum1;

    // Write scaled ctx to g_CTX [b, s, d]
#pragma unroll
    for (int n2 = 0; n2 < 8; n2++) {
        int col = h_ * 64 + n2 * 8 + 2 * qr;
        size_t o0 = ((size_t)(b_ * Sn + q0 + qlo)) * Dn + col;
        *(float2*)&g_CTX[o0] = make_float2(ctx[n2][0] * rinv0, ctx[n2][1] * rinv0);
        size_t o1 = o0 + 8 * Dn;
        *(float2*)&g_CTX[o1] = make_float2(ctx[n2][2] * rinv1, ctx[n2][3] * rinv1);
    }

    if (!attn_out) return;

    // ---------------- Pass B: recompute S, write normalized attn ----------
    for (int kt = 0; kt < 32; kt++) {
        const int k0 = kt * 64;
        __syncthreads();
#pragma unroll
        for (int it = 0; it < 8; it++) {
            int idx = tid + it * 128;
            int row = idx >> 4, c4 = idx & 15;
            float4 kv = *(const float4*)&Kb[(size_t)(k0 + row) * DKn + c4 * 4];
            unsigned* dk_ = &Ks[row * KPAD + c4 * 4];
            dk_[0] = f2tf(kv.x); dk_[1] = f2tf(kv.y); dk_[2] = f2tf(kv.z); dk_[3] = f2tf(kv.w);
        }
        if (tid < 127)
            bias_s[tid] = bias_table[(size_t)(q0 - k0 + MAXSEQ - 1 - 63 + tid) * Hn + h_];
        __syncthreads();

        float sacc[8][4] = {};
#pragma unroll
        for (int kc = 0; kc < 8; kc++) {
#pragma unroll
            for (int ni = 0; ni < 8; ni++) {
                unsigned b0 = Ks[(ni * 8 + g) * KPAD + kc * 8 + qr];
                unsigned b1 = Ks[(ni * 8 + g) * KPAD + kc * 8 + qr + 4];
                mma_tf32(sacc[ni], qa[kc], b0, b1);
            }
        }

        size_t rbase0 = ((size_t)(bh * Sn + q0 + qlo)) * Sn + k0;
        size_t rbase1 = rbase0 + 8 * (size_t)Sn;
#pragma unroll
        for (int ni = 0; ni < 8; ni++) {
            int idx0 = qlo - (ni * 8 + 2 * qr) + 63;
            float p0 = __expf(sacc[ni][0] * 0.125f + bias_s[idx0]) * rinv0;
            float p1 = __expf(sacc[ni][1] * 0.125f + bias_s[idx0 - 1]) * rinv0;
            float p2 = __expf(sacc[ni][2] * 0.125f + bias_s[idx0 + 8]) * rinv1;
            float p3 = __expf(sacc[ni][3] * 0.125f + bias_s[idx0 + 7]) * rinv1;
            int col = ni * 8 + 2 * qr;
            *(float2*)&attn_out[rbase0 + col] = make_float2(p0, p1);
            *(float2*)&attn_out[rbase1 + col] = make_float2(p2, p3);
        }
    }
}

// ---------------------------------------------------------------------------
extern "C" void kernel_launch(void* const* d_in, const int* in_sizes, int n_in,
                              void* d_out, int out_size)
{
    const float* query      = (const float*)d_in[0];
    const float* key        = (const float*)d_in[1];
    const float* value      = (const float*)d_in[2];
    const float* Wq         = (const float*)d_in[3];
    const float* Wk         = (const float*)d_in[4];
    const float* Wv         = (const float*)d_in[5];
    const float* Wo         = (const float*)d_in[6];
    const float* bo         = (const float*)d_in[7];
    const float* bias_table = (const float*)d_in[8];

    float* out = (float*)d_out;
    const bool has_attn = (long long)out_size >= (OUT_ELEMS + ATTN_ELEMS);
    float* attn = has_attn ? out + OUT_ELEMS : nullptr;

    dim3 gproj(1024 / 128, MROWS / 128);   // 8 x 32
    gemm_tc<<<gproj, 256>>>(query, Wq, nullptr, nullptr, 0);
    gemm_tc<<<gproj, 256>>>(key,   Wk, nullptr, nullptr, 1);
    gemm_tc<<<gproj, 256>>>(value, Wv, nullptr, nullptr, 2);

    dim3 gattn(Sn / 64, Bn * Hn);          // 32 x 32
    attn_tc<<<gattn, 128>>>(bias_table, attn);

    gemm_tc<<<gproj, 256>>>(nullptr, Wo, bo, out, 3);
}

// round 4
// speedup vs baseline: 2.6366x; 1.1120x over previous
#include <cuda_runtime.h>

#define Bn 2
#define Sn 2048
#define Dn 1024
#define Hn 16
#define DKn 64
#define MAXSEQ 2048
#define MROWS (Bn * Sn)
#define OUT_ELEMS (MROWS * Dn)
#define ATTN_ELEMS ((long long)Bn * Hn * Sn * Sn)

__device__ float g_Q[Bn * Sn * Dn];
__device__ float g_K[Bn * Sn * Dn];
__device__ float g_V[Bn * Sn * Dn];
__device__ float g_CTX[Bn * Sn * Dn];

__device__ __forceinline__ unsigned f2tf(float x) {
    unsigned u;
    asm("cvt.rna.tf32.f32 %0, %1;" : "=r"(u) : "f"(x));
    return u;
}

__device__ __forceinline__ void mma_tf32(float c[4], const unsigned a[4],
                                         unsigned b0, unsigned b1) {
    asm volatile(
        "mma.sync.aligned.m16n8k8.row.col.f32.tf32.tf32.f32 "
        "{%0,%1,%2,%3}, {%4,%5,%6,%7}, {%8,%9}, {%0,%1,%2,%3};"
        : "+f"(c[0]), "+f"(c[1]), "+f"(c[2]), "+f"(c[3])
        : "r"(a[0]), "r"(a[1]), "r"(a[2]), "r"(a[3]), "r"(b0), "r"(b1));
}

__device__ __forceinline__ void cp_async16(void* dst, const void* src) {
    unsigned s = (unsigned)__cvta_generic_to_shared(dst);
    asm volatile("cp.async.cg.shared.global [%0], [%1], 16;" :: "r"(s), "l"(src));
}
__device__ __forceinline__ void cp_commit() {
    asm volatile("cp.async.commit_group;");
}
template <int N>
__device__ __forceinline__ void cp_wait() {
    asm volatile("cp.async.wait_group %0;" :: "n"(N));
}

// ---------------------------------------------------------------------------
// Projection GEMM, cp.async double-buffered. C[m,n]=sum_k A[m,k]W[n,k] (+bias)
// Block 128x128, 8 warps (2wm x 4wn), warp 64x32, BK=16, 2 stages.
// ---------------------------------------------------------------------------
#define GP 20  // padded words per 16-float row

__global__ __launch_bounds__(256)
void gemm_tc(const float* __restrict__ Aext, const float* __restrict__ W,
             const float* __restrict__ bias, float* __restrict__ Cext, int mode)
{
    __shared__ float As[2][128 * GP];
    __shared__ float Ws[2][128 * GP];

    const float* A = (mode == 3) ? g_CTX : Aext;
    float* C = (mode == 0) ? g_Q : (mode == 1) ? g_K : (mode == 2) ? g_V : Cext;

    const int tid = threadIdx.x;
    const int w = tid >> 5, lane = tid & 31, g = lane >> 2, qr = lane & 3;
    const int wm = w >> 2, wn = w & 3;
    const int m0 = blockIdx.y * 128, n0 = blockIdx.x * 128;
    const int row_f = tid >> 2, c4 = tid & 3;   // fill: 256 thr = 2 float4/thread/matrix

    float c[4][4][4] = {};

    // prefetch stage 0
#pragma unroll
    for (int it = 0; it < 2; it++) {
        int rr = row_f + it * 64;
        cp_async16(&As[0][rr * GP + c4 * 4], &A[(size_t)(m0 + rr) * 1024 + c4 * 4]);
        cp_async16(&Ws[0][rr * GP + c4 * 4], &W[(size_t)(n0 + rr) * 1024 + c4 * 4]);
    }
    cp_commit();

    int st = 0;
    for (int k0 = 0; k0 < 1024; k0 += 16) {
        if (k0 + 16 < 1024) {
#pragma unroll
            for (int it = 0; it < 2; it++) {
                int rr = row_f + it * 64;
                cp_async16(&As[st ^ 1][rr * GP + c4 * 4],
                           &A[(size_t)(m0 + rr) * 1024 + k0 + 16 + c4 * 4]);
                cp_async16(&Ws[st ^ 1][rr * GP + c4 * 4],
                           &W[(size_t)(n0 + rr) * 1024 + k0 + 16 + c4 * 4]);
            }
            cp_commit();
            cp_wait<1>();
        } else {
            cp_wait<0>();
        }
        __syncthreads();

#pragma unroll
        for (int kk = 0; kk < 16; kk += 8) {
            unsigned a[4][4], b[4][2];
#pragma unroll
            for (int mi = 0; mi < 4; mi++) {
                int r = wm * 64 + mi * 16 + g;
                a[mi][0] = f2tf(As[st][r * GP + kk + qr]);
                a[mi][1] = f2tf(As[st][(r + 8) * GP + kk + qr]);
                a[mi][2] = f2tf(As[st][r * GP + kk + qr + 4]);
                a[mi][3] = f2tf(As[st][(r + 8) * GP + kk + qr + 4]);
            }
#pragma unroll
            for (int ni = 0; ni < 4; ni++) {
                int col = wn * 32 + ni * 8 + g;
                b[ni][0] = f2tf(Ws[st][col * GP + kk + qr]);
                b[ni][1] = f2tf(Ws[st][col * GP + kk + qr + 4]);
            }
#pragma unroll
            for (int mi = 0; mi < 4; mi++)
#pragma unroll
                for (int ni = 0; ni < 4; ni++)
                    mma_tf32(c[mi][ni], a[mi], b[ni][0], b[ni][1]);
        }
        __syncthreads();
        st ^= 1;
    }

#pragma unroll
    for (int mi = 0; mi < 4; mi++)
#pragma unroll
        for (int ni = 0; ni < 4; ni++)
#pragma unroll
            for (int half = 0; half < 2; half++) {
                int row = m0 + wm * 64 + mi * 16 + g + half * 8;
                int col = n0 + wn * 32 + ni * 8 + 2 * qr;
                float v0 = c[mi][ni][half * 2 + 0];
                float v1 = c[mi][ni][half * 2 + 1];
                if (mode == 3) {
                    v0 += bias[col];
                    v1 += bias[col + 1];
                    *(float2*)&C[(size_t)row * 1024 + col] = make_float2(v0, v1);
                } else {
                    int b_ = row >> 11, s_ = row & (Sn - 1);
                    int h_ = col >> 6, dk = col & 63;
                    size_t o = (((size_t)(b_ * Hn + h_) * Sn) + s_) * DKn + dk;
                    *(float2*)&C[o] = make_float2(v0, v1);
                }
            }
}

// ---------------------------------------------------------------------------
// Attention, 2x2 warp split: 4 warps, warp (wq,wk) owns 32 q-rows x 32 keys.
// B-fragments reused across both mi => half the K/V fragment traffic.
// Cross-warp ctx reduction via Vs scratch; rowsums via small smem array.
// ---------------------------------------------------------------------------
#define KPAD 68
#define VPAD 72

__global__ __launch_bounds__(128)
void attn_tc(const float* __restrict__ bias_table, float* __restrict__ attn_out)
{
    __shared__ unsigned Ks[64 * KPAD];
    __shared__ unsigned Vs[64 * VPAD];
    __shared__ float bias_s[128];
    __shared__ float rs[2][64];
    __shared__ float rinv_s[64];

    float* Vf = (float*)Vs;

    const int tid = threadIdx.x;
    const int w = tid >> 5, lane = tid & 31, g = lane >> 2, qr = lane & 3;
    const int wq = w >> 1, wk = w & 1;
    const int qt = blockIdx.x, bh = blockIdx.y;
    const int b_ = bh >> 4, h_ = bh & 15;
    const int q0 = qt * 64;

    const float* Qb = g_Q + (size_t)bh * Sn * DKn;
    const float* Kb = g_K + (size_t)bh * Sn * DKn;
    const float* Vb = g_V + (size_t)bh * Sn * DKn;

    // Q fragments: 32 rows x 64 cols per warp -> qa[mi][kc][4]
    unsigned qa[2][8][4];
#pragma unroll
    for (int mi = 0; mi < 2; mi++) {
        const float* r0 = Qb + (size_t)(q0 + wq * 32 + mi * 16 + g) * DKn;
        const float* r1 = r0 + 8 * DKn;
#pragma unroll
        for (int kc = 0; kc < 8; kc++) {
            qa[mi][kc][0] = f2tf(r0[kc * 8 + qr]);
            qa[mi][kc][1] = f2tf(r1[kc * 8 + qr]);
            qa[mi][kc][2] = f2tf(r0[kc * 8 + qr + 4]);
            qa[mi][kc][3] = f2tf(r1[kc * 8 + qr + 4]);
        }
    }

    const int src0 = (lane & 28) | (qr >> 1);
    const int src1 = src0 + 2;
    const bool odd = (qr & 1);

    float ctx[2][8][4] = {};
    float psum[2][2] = {};

    // ---------------- Pass A ----------------
    for (int kt = 0; kt < 32; kt++) {
        const int k0 = kt * 64;
        __syncthreads();
#pragma unroll
        for (int it = 0; it < 8; it++) {
            int idx = tid + it * 128;
            int row = idx >> 4, cc = idx & 15;
            float4 kv = *(const float4*)&Kb[(size_t)(k0 + row) * DKn + cc * 4];
            float4 vv = *(const float4*)&Vb[(size_t)(k0 + row) * DKn + cc * 4];
            unsigned* dk_ = &Ks[row * KPAD + cc * 4];
            unsigned* dv_ = &Vs[row * VPAD + cc * 4];
            dk_[0] = f2tf(kv.x); dk_[1] = f2tf(kv.y); dk_[2] = f2tf(kv.z); dk_[3] = f2tf(kv.w);
            dv_[0] = f2tf(vv.x); dv_[1] = f2tf(vv.y); dv_[2] = f2tf(vv.z); dv_[3] = f2tf(vv.w);
        }
        if (tid < 127)
            bias_s[tid] = bias_table[(size_t)(q0 - k0 + MAXSEQ - 1 - 63 + tid) * Hn + h_];
        __syncthreads();

        // S = Q K^T : each warp 32q x 32k
        float sacc[2][4][4] = {};
#pragma unroll
        for (int kc = 0; kc < 8; kc++) {
#pragma unroll
            for (int ni = 0; ni < 4; ni++) {
                int col = wk * 32 + ni * 8 + g;
                unsigned b0 = Ks[col * KPAD + kc * 8 + qr];
                unsigned b1 = Ks[col * KPAD + kc * 8 + qr + 4];
                mma_tf32(sacc[0][ni], qa[0][kc], b0, b1);
                mma_tf32(sacc[1][ni], qa[1][kc], b0, b1);
            }
        }

        // exp + bias, psum, convert to A-frags
        unsigned pA[2][4][4];
#pragma unroll
        for (int mi = 0; mi < 2; mi++)
#pragma unroll
            for (int ni = 0; ni < 4; ni++) {
                int qi = wq * 32 + mi * 16 + g;
                int kj = wk * 32 + ni * 8 + 2 * qr;
                int idx0 = qi - kj + 63;
                float p0 = __expf(sacc[mi][ni][0] * 0.125f + bias_s[idx0]);
                float p1 = __expf(sacc[mi][ni][1] * 0.125f + bias_s[idx0 - 1]);
                float p2 = __expf(sacc[mi][ni][2] * 0.125f + bias_s[idx0 + 8]);
                float p3 = __expf(sacc[mi][ni][3] * 0.125f + bias_s[idx0 + 7]);
                psum[mi][0] += p0 + p1;
                psum[mi][1] += p2 + p3;
                float u0 = __shfl_sync(0xffffffffu, p0, src0);
                float u1 = __shfl_sync(0xffffffffu, p1, src0);
                pA[mi][ni][0] = f2tf(odd ? u1 : u0);
                float u2 = __shfl_sync(0xffffffffu, p2, src0);
                float u3 = __shfl_sync(0xffffffffu, p3, src0);
                pA[mi][ni][1] = f2tf(odd ? u3 : u2);
                float u4 = __shfl_sync(0xffffffffu, p0, src1);
                float u5 = __shfl_sync(0xffffffffu, p1, src1);
                pA[mi][ni][2] = f2tf(odd ? u5 : u4);
                float u6 = __shfl_sync(0xffffffffu, p2, src1);
                float u7 = __shfl_sync(0xffffffffu, p3, src1);
                pA[mi][ni][3] = f2tf(odd ? u7 : u6);
            }

        // ctx += P @ V  (warp's 32-key slice)
#pragma unroll
        for (int kc2 = 0; kc2 < 4; kc2++) {
#pragma unroll
            for (int n2 = 0; n2 < 8; n2++) {
                int krow = wk * 32 + kc2 * 8 + qr;
                unsigned b0 = Vs[krow * VPAD + n2 * 8 + g];
                unsigned b1 = Vs[(krow + 4) * VPAD + n2 * 8 + g];
                mma_tf32(ctx[0][n2], pA[0][kc2], b0, b1);
                mma_tf32(ctx[1][n2], pA[1][kc2], b0, b1);
            }
        }
    }

    // Rowsums: reduce qr lanes, publish per (wk)
#pragma unroll
    for (int mi = 0; mi < 2; mi++)
#pragma unroll
        for (int h2 = 0; h2 < 2; h2++) {
            float v = psum[mi][h2];
            v += __shfl_xor_sync(0xffffffffu, v, 1);
            v += __shfl_xor_sync(0xffffffffu, v, 2);
            if (qr == 0) rs[wk][wq * 32 + mi * 16 + h2 * 8 + g] = v;
        }
    __syncthreads();   // also: all PV reads of Vs done before scratch reuse

    // wk==1 parks its ctx partials in Vs scratch
    if (wk == 1) {
#pragma unroll
        for (int mi = 0; mi < 2; mi++)
#pragma unroll
            for (int n2 = 0; n2 < 8; n2++) {
                int row = wq * 32 + mi * 16 + g;
                *(float2*)&Vf[row * VPAD + n2 * 8 + 2 * qr] =
                    make_float2(ctx[mi][n2][0], ctx[mi][n2][1]);
                *(float2*)&Vf[(row + 8) * VPAD + n2 * 8 + 2 * qr] =
                    make_float2(ctx[mi][n2][2], ctx[mi][n2][3]);
            }
    }
    if (tid < 64) rinv_s[tid] = 1.0f / (rs[0][tid] + rs[1][tid]);
    __syncthreads();

    // wk==0 combines, scales, writes g_CTX [b,s,d]
    if (wk == 0) {
#pragma unroll
        for (int mi = 0; mi < 2; mi++)
#pragma unroll
            for (int n2 = 0; n2 < 8; n2++) {
                int row = wq * 32 + mi * 16 + g;
                float2 o0 = *(float2*)&Vf[row * VPAD + n2 * 8 + 2 * qr];
                float2 o1 = *(float2*)&Vf[(row + 8) * VPAD + n2 * 8 + 2 * qr];
                float r0 = rinv_s[row], r1 = rinv_s[row + 8];
                int col = h_ * 64 + n2 * 8 + 2 * qr;
                size_t a0 = ((size_t)(b_ * Sn + q0 + row)) * Dn + col;
                *(float2*)&g_CTX[a0] =
                    make_float2((ctx[mi][n2][0] + o0.x) * r0, (ctx[mi][n2][1] + o0.y) * r0);
                *(float2*)&g_CTX[a0 + 8 * Dn] =
                    make_float2((ctx[mi][n2][2] + o1.x) * r1, (ctx[mi][n2][3] + o1.y) * r1);
            }
    }

    if (!attn_out) return;

    float rv[2][2];
#pragma unroll
    for (int mi = 0; mi < 2; mi++) {
        rv[mi][0] = rinv_s[wq * 32 + mi * 16 + g];
        rv[mi][1] = rinv_s[wq * 32 + mi * 16 + g + 8];
    }

    // ---------------- Pass B: recompute S, write normalized attn ----------
    for (int kt = 0; kt < 32; kt++) {
        const int k0 = kt * 64;
        __syncthreads();
#pragma unroll
        for (int it = 0; it < 8; it++) {
            int idx = tid + it * 128;
            int row = idx >> 4, cc = idx & 15;
            float4 kv = *(const float4*)&Kb[(size_t)(k0 + row) * DKn + cc * 4];
            unsigned* dk_ = &Ks[row * KPAD + cc * 4];
            dk_[0] = f2tf(kv.x); dk_[1] = f2tf(kv.y); dk_[2] = f2tf(kv.z); dk_[3] = f2tf(kv.w);
        }
        if (tid < 127)
            bias_s[tid] = bias_table[(size_t)(q0 - k0 + MAXSEQ - 1 - 63 + tid) * Hn + h_];
        __syncthreads();

        float sacc[2][4][4] = {};
#pragma unroll
        for (int kc = 0; kc < 8; kc++) {
#pragma unroll
            for (int ni = 0; ni < 4; ni++) {
                int col = wk * 32 + ni * 8 + g;
                unsigned b0 = Ks[col * KPAD + kc * 8 + qr];
                unsigned b1 = Ks[col * KPAD + kc * 8 + qr + 4];
                mma_tf32(sacc[0][ni], qa[0][kc], b0, b1);
                mma_tf32(sacc[1][ni], qa[1][kc], b0, b1);
            }
        }

#pragma unroll
        for (int mi = 0; mi < 2; mi++) {
            int qi = wq * 32 + mi * 16 + g;
            size_t rbase0 = ((size_t)(bh * Sn + q0 + qi)) * Sn + k0;
            size_t rbase1 = rbase0 + 8 * (size_t)Sn;
#pragma unroll
            for (int ni = 0; ni < 4; ni++) {
                int kj = wk * 32 + ni * 8 + 2 * qr;
                int idx0 = qi - kj + 63;
                float p0 = __expf(sacc[mi][ni][0] * 0.125f + bias_s[idx0]) * rv[mi][0];
                float p1 = __expf(sacc[mi][ni][1] * 0.125f + bias_s[idx0 - 1]) * rv[mi][0];
                float p2 = __expf(sacc[mi][ni][2] * 0.125f + bias_s[idx0 + 8]) * rv[mi][1];
                float p3 = __expf(sacc[mi][ni][3] * 0.125f + bias_s[idx0 + 7]) * rv[mi][1];
                *(float2*)&attn_out[rbase0 + kj] = make_float2(p0, p1);
                *(float2*)&attn_out[rbase1 + kj] = make_float2(p2, p3);
            }
        }
    }
}

// ---------------------------------------------------------------------------
extern "C" void kernel_launch(void* const* d_in, const int* in_sizes, int n_in,
                              void* d_out, int out_size)
{
    const float* query      = (const float*)d_in[0];
    const float* key        = (const float*)d_in[1];
    const float* value      = (const float*)d_in[2];
    const float* Wq         = (const float*)d_in[3];
    const float* Wk         = (const float*)d_in[4];
    const float* Wv         = (const float*)d_in[5];
    const float* Wo         = (const float*)d_in[6];
    const float* bo         = (const float*)d_in[7];
    const float* bias_table = (const float*)d_in[8];

    float* out = (float*)d_out;
    const bool has_attn = (long long)out_size >= (OUT_ELEMS + ATTN_ELEMS);
    float* attn = has_attn ? out + OUT_ELEMS : nullptr;

    dim3 gproj(1024 / 128, MROWS / 128);   // 8 x 32
    gemm_tc<<<gproj, 256>>>(query, Wq, nullptr, nullptr, 0);
    gemm_tc<<<gproj, 256>>>(key,   Wk, nullptr, nullptr, 1);
    gemm_tc<<<gproj, 256>>>(value, Wv, nullptr, nullptr, 2);

    dim3 gattn(Sn / 64, Bn * Hn);          // 32 x 32
    attn_tc<<<gattn, 128>>>(bias_table, attn);

    gemm_tc<<<gproj, 256>>>(nullptr, Wo, bo, out, 3);
}

// round 6
// speedup vs baseline: 2.6743x; 1.0143x over previous
#include <cuda_runtime.h>

#define Bn 2
#define Sn 2048
#define Dn 1024
#define Hn 16
#define DKn 64
#define MAXSEQ 2048
#define MROWS (Bn * Sn)
#define OUT_ELEMS (MROWS * Dn)
#define ATTN_ELEMS ((long long)Bn * Hn * Sn * Sn)

__device__ float g_Q[Bn * Sn * Dn];
__device__ float g_K[Bn * Sn * Dn];
__device__ float g_V[Bn * Sn * Dn];
__device__ float g_CTX[Bn * Sn * Dn];

__device__ __forceinline__ unsigned f2tf(float x) {
    unsigned u;
    asm("cvt.rna.tf32.f32 %0, %1;" : "=r"(u) : "f"(x));
    return u;
}

__device__ __forceinline__ void mma_tf32(float c[4], const unsigned a[4],
                                         unsigned b0, unsigned b1) {
    asm volatile(
        "mma.sync.aligned.m16n8k8.row.col.f32.tf32.tf32.f32 "
        "{%0,%1,%2,%3}, {%4,%5,%6,%7}, {%8,%9}, {%0,%1,%2,%3};"
        : "+f"(c[0]), "+f"(c[1]), "+f"(c[2]), "+f"(c[3])
        : "r"(a[0]), "r"(a[1]), "r"(a[2]), "r"(a[3]), "r"(b0), "r"(b1));
}

__device__ __forceinline__ void cp_async16(void* dst, const void* src) {
    unsigned s = (unsigned)__cvta_generic_to_shared(dst);
    asm volatile("cp.async.cg.shared.global [%0], [%1], 16;" :: "r"(s), "l"(src));
}
__device__ __forceinline__ void cp_async4(void* dst, const void* src) {
    unsigned s = (unsigned)__cvta_generic_to_shared(dst);
    asm volatile("cp.async.ca.shared.global [%0], [%1], 4;" :: "r"(s), "l"(src));
}
__device__ __forceinline__ void cp_commit() {
    asm volatile("cp.async.commit_group;");
}
template <int N>
__device__ __forceinline__ void cp_wait() {
    asm volatile("cp.async.wait_group %0;" :: "n"(N));
}

// ---------------------------------------------------------------------------
// Projection GEMM, cp.async double-buffered (unchanged from R4, passing).
// ---------------------------------------------------------------------------
#define GP 20

__global__ __launch_bounds__(256)
void gemm_tc(const float* __restrict__ Aext, const float* __restrict__ W,
             const float* __restrict__ bias, float* __restrict__ Cext, int mode)
{
    __shared__ float As[2][128 * GP];
    __shared__ float Ws[2][128 * GP];

    const float* A = (mode == 3) ? g_CTX : Aext;
    float* C = (mode == 0) ? g_Q : (mode == 1) ? g_K : (mode == 2) ? g_V : Cext;

    const int tid = threadIdx.x;
    const int w = tid >> 5, lane = tid & 31, g = lane >> 2, qr = lane & 3;
    const int wm = w >> 2, wn = w & 3;
    const int m0 = blockIdx.y * 128, n0 = blockIdx.x * 128;
    const int row_f = tid >> 2, c4 = tid & 3;

    float c[4][4][4] = {};

#pragma unroll
    for (int it = 0; it < 2; it++) {
        int rr = row_f + it * 64;
        cp_async16(&As[0][rr * GP + c4 * 4], &A[(size_t)(m0 + rr) * 1024 + c4 * 4]);
        cp_async16(&Ws[0][rr * GP + c4 * 4], &W[(size_t)(n0 + rr) * 1024 + c4 * 4]);
    }
    cp_commit();

    int st = 0;
    for (int k0 = 0; k0 < 1024; k0 += 16) {
        if (k0 + 16 < 1024) {
#pragma unroll
            for (int it = 0; it < 2; it++) {
                int rr = row_f + it * 64;
                cp_async16(&As[st ^ 1][rr * GP + c4 * 4],
                           &A[(size_t)(m0 + rr) * 1024 + k0 + 16 + c4 * 4]);
                cp_async16(&Ws[st ^ 1][rr * GP + c4 * 4],
                           &W[(size_t)(n0 + rr) * 1024 + k0 + 16 + c4 * 4]);
            }
            cp_commit();
            cp_wait<1>();
        } else {
            cp_wait<0>();
        }
        __syncthreads();

#pragma unroll
        for (int kk = 0; kk < 16; kk += 8) {
            unsigned a[4][4], b[4][2];
#pragma unroll
            for (int mi = 0; mi < 4; mi++) {
                int r = wm * 64 + mi * 16 + g;
                a[mi][0] = f2tf(As[st][r * GP + kk + qr]);
                a[mi][1] = f2tf(As[st][(r + 8) * GP + kk + qr]);
                a[mi][2] = f2tf(As[st][r * GP + kk + qr + 4]);
                a[mi][3] = f2tf(As[st][(r + 8) * GP + kk + qr + 4]);
            }
#pragma unroll
            for (int ni = 0; ni < 4; ni++) {
                int col = wn * 32 + ni * 8 + g;
                b[ni][0] = f2tf(Ws[st][col * GP + kk + qr]);
                b[ni][1] = f2tf(Ws[st][col * GP + kk + qr + 4]);
            }
#pragma unroll
            for (int mi = 0; mi < 4; mi++)
#pragma unroll
                for (int ni = 0; ni < 4; ni++)
                    mma_tf32(c[mi][ni], a[mi], b[ni][0], b[ni][1]);
        }
        __syncthreads();
        st ^= 1;
    }

#pragma unroll
    for (int mi = 0; mi < 4; mi++)
#pragma unroll
        for (int ni = 0; ni < 4; ni++)
#pragma unroll
            for (int half = 0; half < 2; half++) {
                int row = m0 + wm * 64 + mi * 16 + g + half * 8;
                int col = n0 + wn * 32 + ni * 8 + 2 * qr;
                float v0 = c[mi][ni][half * 2 + 0];
                float v1 = c[mi][ni][half * 2 + 1];
                if (mode == 3) {
                    v0 += bias[col];
                    v1 += bias[col + 1];
                    *(float2*)&C[(size_t)row * 1024 + col] = make_float2(v0, v1);
                } else {
                    int b_ = row >> 11, s_ = row & (Sn - 1);
                    int h_ = col >> 6, dk = col & 63;
                    size_t o = (((size_t)(b_ * Hn + h_) * Sn) + s_) * DKn + dk;
                    *(float2*)&C[o] = make_float2(v0, v1);
                }
            }
}

// ---------------------------------------------------------------------------
// Attention: 8 warps (4q x 2k), warp tile 16q x 32k over a 64-q block tile.
// cp.async double-buffered raw K/V (+bias); tf32 convert at fragment load.
// Fill mapping (FIXED): 64 rows x 16 float4; idx = tid + it*256, row=idx>>4.
// ---------------------------------------------------------------------------
#define KROW 68
#define VROW 72
#define KTILE (64 * KROW)
#define VTILE (64 * VROW)
#define ATTN_SMEM ((2 * KTILE + 2 * VTILE) * 4)

__global__ __launch_bounds__(256)
void attn_tc(const float* __restrict__ bias_table, float* __restrict__ attn_out)
{
    extern __shared__ float sm[];
    float* KsF = sm;                 // [2][KTILE]
    float* VsF = sm + 2 * KTILE;     // [2][VTILE]
    __shared__ float bias_s[2][128];
    __shared__ float rs[2][64];
    __shared__ float rinv_s[64];

    const int tid = threadIdx.x;
    const int w = tid >> 5, lane = tid & 31, g = lane >> 2, qr = lane & 3;
    const int wq = w >> 1, wk = w & 1;
    const int qt = blockIdx.x, bh = blockIdx.y;
    const int b_ = bh >> 4, h_ = bh & 15;
    const int q0 = qt * 64;
    const int qlo = wq * 16 + g;

    const float* Qb = g_Q + (size_t)bh * Sn * DKn;
    const float* Kb = g_K + (size_t)bh * Sn * DKn;
    const float* Vb = g_V + (size_t)bh * Sn * DKn;
    const float* bias_base = bias_table + (size_t)(q0 + MAXSEQ - 1 - 63) * Hn + h_;

    // Q fragments: 16 rows x 64 cols per warp
    unsigned qa[8][4];
    {
        const float* r0 = Qb + (size_t)(q0 + qlo) * DKn;
        const float* r1 = r0 + 8 * DKn;
#pragma unroll
        for (int kc = 0; kc < 8; kc++) {
            qa[kc][0] = f2tf(r0[kc * 8 + qr]);
            qa[kc][1] = f2tf(r1[kc * 8 + qr]);
            qa[kc][2] = f2tf(r0[kc * 8 + qr + 4]);
            qa[kc][3] = f2tf(r1[kc * 8 + qr + 4]);
        }
    }

    const int src0 = (lane & 28) | (qr >> 1);
    const int src1 = src0 + 2;
    const bool odd = (qr & 1);

    float ctx[8][4] = {};
    float psum[2] = {};

    // Prologue: prefetch tile 0 (K, V, bias) into buffer 0
    {
#pragma unroll
        for (int it = 0; it < 4; it++) {
            int idx = tid + it * 256;            // 1024 float4 units
            int row = idx >> 4, cc = idx & 15;
            cp_async16(&KsF[row * KROW + cc * 4], &Kb[(size_t)row * DKn + cc * 4]);
            cp_async16(&VsF[row * VROW + cc * 4], &Vb[(size_t)row * DKn + cc * 4]);
        }
        if (tid < 127) cp_async4(&bias_s[0][tid], bias_base + (size_t)tid * Hn);
        cp_commit();
    }

    // ---------------- Pass A ----------------
    for (int kt = 0; kt < 32; kt++) {
        const int st = kt & 1;
        cp_wait<0>();
        __syncthreads();

        if (kt + 1 < 32) {
            const int k1 = (kt + 1) * 64;
            const float* Kn = Kb + (size_t)k1 * DKn;
            const float* Vn = Vb + (size_t)k1 * DKn;
            float* Kd = KsF + (st ^ 1) * KTILE;
            float* Vd = VsF + (st ^ 1) * VTILE;
#pragma unroll
            for (int it = 0; it < 4; it++) {
                int idx = tid + it * 256;
                int row = idx >> 4, cc = idx & 15;
                cp_async16(&Kd[row * KROW + cc * 4], &Kn[(size_t)row * DKn + cc * 4]);
                cp_async16(&Vd[row * VROW + cc * 4], &Vn[(size_t)row * DKn + cc * 4]);
            }
            if (tid < 127)
                cp_async4(&bias_s[st ^ 1][tid], bias_base + (size_t)(tid - k1) * Hn);
            cp_commit();
        }

        const float* Kt = KsF + st * KTILE;
        const float* Vt = VsF + st * VTILE;

        // S = Q K^T : 16q x 32k per warp
        float sacc[4][4] = {};
#pragma unroll
        for (int kc = 0; kc < 8; kc++) {
#pragma unroll
            for (int ni = 0; ni < 4; ni++) {
                int col = wk * 32 + ni * 8 + g;
                unsigned b0 = f2tf(Kt[col * KROW + kc * 8 + qr]);
                unsigned b1 = f2tf(Kt[col * KROW + kc * 8 + qr + 4]);
                mma_tf32(sacc[ni], qa[kc], b0, b1);
            }
        }

        // exp + bias, psum, convert to A-frags
        unsigned pA[4][4];
#pragma unroll
        for (int ni = 0; ni < 4; ni++) {
            int kj = wk * 32 + ni * 8 + 2 * qr;
            int idx0 = qlo - kj + 63;
            float p0 = __expf(sacc[ni][0] * 0.125f + bias_s[st][idx0]);
            float p1 = __expf(sacc[ni][1] * 0.125f + bias_s[st][idx0 - 1]);
            float p2 = __expf(sacc[ni][2] * 0.125f + bias_s[st][idx0 + 8]);
            float p3 = __expf(sacc[ni][3] * 0.125f + bias_s[st][idx0 + 7]);
            psum[0] += p0 + p1;
            psum[1] += p2 + p3;
            float u0 = __shfl_sync(0xffffffffu, p0, src0);
            float u1 = __shfl_sync(0xffffffffu, p1, src0);
            pA[ni][0] = f2tf(odd ? u1 : u0);
            float u2 = __shfl_sync(0xffffffffu, p2, src0);
            float u3 = __shfl_sync(0xffffffffu, p3, src0);
            pA[ni][1] = f2tf(odd ? u3 : u2);
            float u4 = __shfl_sync(0xffffffffu, p0, src1);
            float u5 = __shfl_sync(0xffffffffu, p1, src1);
            pA[ni][2] = f2tf(odd ? u5 : u4);
            float u6 = __shfl_sync(0xffffffffu, p2, src1);
            float u7 = __shfl_sync(0xffffffffu, p3, src1);
            pA[ni][3] = f2tf(odd ? u7 : u6);
        }

        // ctx += P @ V  (warp's 32-key slice)
#pragma unroll
        for (int kc2 = 0; kc2 < 4; kc2++) {
            int krow = wk * 32 + kc2 * 8 + qr;
#pragma unroll
            for (int n2 = 0; n2 < 8; n2++) {
                unsigned b0 = f2tf(Vt[krow * VROW + n2 * 8 + g]);
                unsigned b1 = f2tf(Vt[(krow + 4) * VROW + n2 * 8 + g]);
                mma_tf32(ctx[n2], pA[kc2], b0, b1);
            }
        }
    }

    // Rowsums per wk half
#pragma unroll
    for (int h2 = 0; h2 < 2; h2++) {
        float v = psum[h2];
        v += __shfl_xor_sync(0xffffffffu, v, 1);
        v += __shfl_xor_sync(0xffffffffu, v, 2);
        if (qr == 0) rs[wk][wq * 16 + h2 * 8 + g] = v;
    }
    __syncthreads();   // compute done; safe to reuse KsF[0] as scratch

    float* Kf = KsF;   // scratch: 64 rows x 64 cols (stride KROW)
    if (wk == 1) {
#pragma unroll
        for (int n2 = 0; n2 < 8; n2++) {
            *(float2*)&Kf[qlo * KROW + n2 * 8 + 2 * qr] =
                make_float2(ctx[n2][0], ctx[n2][1]);
            *(float2*)&Kf[(qlo + 8) * KROW + n2 * 8 + 2 * qr] =
                make_float2(ctx[n2][2], ctx[n2][3]);
        }
    }
    if (tid < 64) rinv_s[tid] = 1.0f / (rs[0][tid] + rs[1][tid]);
    __syncthreads();

    if (wk == 0) {
        float r0 = rinv_s[qlo], r1 = rinv_s[qlo + 8];
#pragma unroll
        for (int n2 = 0; n2 < 8; n2++) {
            float2 o0 = *(float2*)&Kf[qlo * KROW + n2 * 8 + 2 * qr];
            float2 o1 = *(float2*)&Kf[(qlo + 8) * KROW + n2 * 8 + 2 * qr];
            int col = h_ * 64 + n2 * 8 + 2 * qr;
            size_t a0 = ((size_t)(b_ * Sn + q0 + qlo)) * Dn + col;
            *(float2*)&g_CTX[a0] =
                make_float2((ctx[n2][0] + o0.x) * r0, (ctx[n2][1] + o0.y) * r0);
            *(float2*)&g_CTX[a0 + 8 * Dn] =
                make_float2((ctx[n2][2] + o1.x) * r1, (ctx[n2][3] + o1.y) * r1);
        }
    }

    if (!attn_out) return;

    const float rv0 = rinv_s[qlo];
    const float rv1 = rinv_s[qlo + 8];
    __syncthreads();   // scratch reads done before prefetch overwrites KsF[0]

    // ---------------- Pass B ----------------
    {
#pragma unroll
        for (int it = 0; it < 4; it++) {
            int idx = tid + it * 256;
            int row = idx >> 4, cc = idx & 15;
            cp_async16(&KsF[row * KROW + cc * 4], &Kb[(size_t)row * DKn + cc * 4]);
        }
        if (tid < 127) cp_async4(&bias_s[0][tid], bias_base + (size_t)tid * Hn);
        cp_commit();
    }

    for (int kt = 0; kt < 32; kt++) {
        const int st = kt & 1;
        const int k0 = kt * 64;
        cp_wait<0>();
        __syncthreads();

        if (kt + 1 < 32) {
            const int k1 = (kt + 1) * 64;
            const float* Kn = Kb + (size_t)k1 * DKn;
            float* Kd = KsF + (st ^ 1) * KTILE;
#pragma unroll
            for (int it = 0; it < 4; it++) {
                int idx = tid + it * 256;
                int row = idx >> 4, cc = idx & 15;
                cp_async16(&Kd[row * KROW + cc * 4], &Kn[(size_t)row * DKn + cc * 4]);
            }
            if (tid < 127)
                cp_async4(&bias_s[st ^ 1][tid], bias_base + (size_t)(tid - k1) * Hn);
            cp_commit();
        }

        const float* Kt = KsF + st * KTILE;

        float sacc[4][4] = {};
#pragma unroll
        for (int kc = 0; kc < 8; kc++) {
#pragma unroll
            for (int ni = 0; ni < 4; ni++) {
                int col = wk * 32 + ni * 8 + g;
                unsigned b0 = f2tf(Kt[col * KROW + kc * 8 + qr]);
                unsigned b1 = f2tf(Kt[col * KROW + kc * 8 + qr + 4]);
                mma_tf32(sacc[ni], qa[kc], b0, b1);
            }
        }

        size_t rbase0 = ((size_t)(bh * Sn + q0 + qlo)) * Sn + k0;
        size_t rbase1 = rbase0 + 8 * (size_t)Sn;
#pragma unroll
        for (int ni = 0; ni < 4; ni++) {
            int kj = wk * 32 + ni * 8 + 2 * qr;
            int idx0 = qlo - kj + 63;
            float p0 = __expf(sacc[ni][0] * 0.125f + bias_s[st][idx0]) * rv0;
            float p1 = __expf(sacc[ni][1] * 0.125f + bias_s[st][idx0 - 1]) * rv0;
            float p2 = __expf(sacc[ni][2] * 0.125f + bias_s[st][idx0 + 8]) * rv1;
            float p3 = __expf(sacc[ni][3] * 0.125f + bias_s[st][idx0 + 7]) * rv1;
            *(float2*)&attn_out[rbase0 + kj] = make_float2(p0, p1);
            *(float2*)&attn_out[rbase1 + kj] = make_float2(p2, p3);
        }
    }
}

// ---------------------------------------------------------------------------
extern "C" void kernel_launch(void* const* d_in, const int* in_sizes, int n_in,
                              void* d_out, int out_size)
{
    const float* query      = (const float*)d_in[0];
    const float* key        = (const float*)d_in[1];
    const float* value      = (const float*)d_in[2];
    const float* Wq         = (const float*)d_in[3];
    const float* Wk         = (const float*)d_in[4];
    const float* Wv         = (const float*)d_in[5];
    const float* Wo         = (const float*)d_in[6];
    const float* bo         = (const float*)d_in[7];
    const float* bias_table = (const float*)d_in[8];

    float* out = (float*)d_out;
    const bool has_attn = (long long)out_size >= (OUT_ELEMS + ATTN_ELEMS);
    float* attn = has_attn ? out + OUT_ELEMS : nullptr;

    cudaFuncSetAttribute(attn_tc, cudaFuncAttributeMaxDynamicSharedMemorySize,
                         ATTN_SMEM);

    dim3 gproj(1024 / 128, MROWS / 128);   // 8 x 32
    gemm_tc<<<gproj, 256>>>(query, Wq, nullptr, nullptr, 0);
    gemm_tc<<<gproj, 256>>>(key,   Wk, nullptr, nullptr, 1);
    gemm_tc<<<gproj, 256>>>(value, Wv, nullptr, nullptr, 2);

    dim3 gattn(Sn / 64, Bn * Hn);          // 32 x 32
    attn_tc<<<gattn, 256, ATTN_SMEM>>>(bias_table, attn);

    gemm_tc<<<gproj, 256>>>(nullptr, Wo, bo, out, 3);
}

// round 7
// speedup vs baseline: 2.7762x; 1.0381x over previous
#include <cuda_runtime.h>

#define Bn 2
#define Sn 2048
#define Dn 1024
#define Hn 16
#define DKn 64
#define MAXSEQ 2048
#define MROWS (Bn * Sn)
#define OUT_ELEMS (MROWS * Dn)
#define ATTN_ELEMS ((long long)Bn * Hn * Sn * Sn)

__device__ float g_Q[Bn * Sn * Dn];
__device__ float g_K[Bn * Sn * Dn];
__device__ float g_V[Bn * Sn * Dn];
__device__ float g_CTX[Bn * Sn * Dn];
// pre-rounded (tf32-valued fp32) copies of inputs
__device__ float g_RQ[Bn * Sn * Dn];
__device__ float g_RK[Bn * Sn * Dn];
__device__ float g_RV[Bn * Sn * Dn];
__device__ float g_WQ[Dn * Dn];
__device__ float g_WK[Dn * Dn];
__device__ float g_WV[Dn * Dn];
__device__ float g_WO[Dn * Dn];

__device__ __forceinline__ unsigned f2tf(float x) {
    unsigned u;
    asm("cvt.rna.tf32.f32 %0, %1;" : "=r"(u) : "f"(x));
    return u;
}

__device__ __forceinline__ void mma_tf32(float c[4], const unsigned a[4],
                                         unsigned b0, unsigned b1) {
    asm volatile(
        "mma.sync.aligned.m16n8k8.row.col.f32.tf32.tf32.f32 "
        "{%0,%1,%2,%3}, {%4,%5,%6,%7}, {%8,%9}, {%0,%1,%2,%3};"
        : "+f"(c[0]), "+f"(c[1]), "+f"(c[2]), "+f"(c[3])
        : "r"(a[0]), "r"(a[1]), "r"(a[2]), "r"(a[3]), "r"(b0), "r"(b1));
}

__device__ __forceinline__ void cp_async16(void* dst, const void* src) {
    unsigned s = (unsigned)__cvta_generic_to_shared(dst);
    asm volatile("cp.async.cg.shared.global [%0], [%1], 16;" :: "r"(s), "l"(src));
}
__device__ __forceinline__ void cp_async4(void* dst, const void* src) {
    unsigned s = (unsigned)__cvta_generic_to_shared(dst);
    asm volatile("cp.async.ca.shared.global [%0], [%1], 4;" :: "r"(s), "l"(src));
}
__device__ __forceinline__ void cp_commit() {
    asm volatile("cp.async.commit_group;");
}
template <int N>
__device__ __forceinline__ void cp_wait() {
    asm volatile("cp.async.wait_group %0;" :: "n"(N));
}

// ---------------------------------------------------------------------------
// Elementwise tf32 pre-rounding: dst[i] = round_tf32(src[i]) (float4 strided)
// ---------------------------------------------------------------------------
__global__ __launch_bounds__(256)
void round_kernel(const float* __restrict__ s, float* __restrict__ d, int n4)
{
    int i = blockIdx.x * blockDim.x + threadIdx.x;
    if (i < n4) {
        float4 v = ((const float4*)s)[i];
        v.x = __uint_as_float(f2tf(v.x));
        v.y = __uint_as_float(f2tf(v.y));
        v.z = __uint_as_float(f2tf(v.z));
        v.w = __uint_as_float(f2tf(v.w));
        ((float4*)d)[i] = v;
    }
}

// ---------------------------------------------------------------------------
// Projection GEMM: inputs pre-rounded => no CVT in hot loop.
// mode 0/1/2: C = g_Q/g_K/g_V stored tf32-ROUNDED, layout [b,h,s,dk]
// mode 3:     A = g_CTX (pre-rounded), C = d_out + bias, raw fp32
// ---------------------------------------------------------------------------
#define GP 20

__global__ __launch_bounds__(256)
void gemm_tc(const float* __restrict__ A, const float* __restrict__ W,
             const float* __restrict__ bias, float* __restrict__ Cext, int mode)
{
    __shared__ float As[2][128 * GP];
    __shared__ float Ws[2][128 * GP];

    float* C = (mode == 0) ? g_Q : (mode == 1) ? g_K : (mode == 2) ? g_V : Cext;

    const int tid = threadIdx.x;
    const int w = tid >> 5, lane = tid & 31, g = lane >> 2, qr = lane & 3;
    const int wm = w >> 2, wn = w & 3;
    const int m0 = blockIdx.y * 128, n0 = blockIdx.x * 128;
    const int row_f = tid >> 2, c4 = tid & 3;

    float c[4][4][4] = {};

#pragma unroll
    for (int it = 0; it < 2; it++) {
        int rr = row_f + it * 64;
        cp_async16(&As[0][rr * GP + c4 * 4], &A[(size_t)(m0 + rr) * 1024 + c4 * 4]);
        cp_async16(&Ws[0][rr * GP + c4 * 4], &W[(size_t)(n0 + rr) * 1024 + c4 * 4]);
    }
    cp_commit();

    int st = 0;
    for (int k0 = 0; k0 < 1024; k0 += 16) {
        if (k0 + 16 < 1024) {
#pragma unroll
            for (int it = 0; it < 2; it++) {
                int rr = row_f + it * 64;
                cp_async16(&As[st ^ 1][rr * GP + c4 * 4],
                           &A[(size_t)(m0 + rr) * 1024 + k0 + 16 + c4 * 4]);
                cp_async16(&Ws[st ^ 1][rr * GP + c4 * 4],
                           &W[(size_t)(n0 + rr) * 1024 + k0 + 16 + c4 * 4]);
            }
            cp_commit();
            cp_wait<1>();
        } else {
            cp_wait<0>();
        }
        __syncthreads();

#pragma unroll
        for (int kk = 0; kk < 16; kk += 8) {
            unsigned a[4][4], b[4][2];
#pragma unroll
            for (int mi = 0; mi < 4; mi++) {
                int r = wm * 64 + mi * 16 + g;
                a[mi][0] = __float_as_uint(As[st][r * GP + kk + qr]);
                a[mi][1] = __float_as_uint(As[st][(r + 8) * GP + kk + qr]);
                a[mi][2] = __float_as_uint(As[st][r * GP + kk + qr + 4]);
                a[mi][3] = __float_as_uint(As[st][(r + 8) * GP + kk + qr + 4]);
            }
#pragma unroll
            for (int ni = 0; ni < 4; ni++) {
                int col = wn * 32 + ni * 8 + g;
                b[ni][0] = __float_as_uint(Ws[st][col * GP + kk + qr]);
                b[ni][1] = __float_as_uint(Ws[st][col * GP + kk + qr + 4]);
            }
#pragma unroll
            for (int mi = 0; mi < 4; mi++)
#pragma unroll
                for (int ni = 0; ni < 4; ni++)
                    mma_tf32(c[mi][ni], a[mi], b[ni][0], b[ni][1]);
        }
        __syncthreads();
        st ^= 1;
    }

#pragma unroll
    for (int mi = 0; mi < 4; mi++)
#pragma unroll
        for (int ni = 0; ni < 4; ni++)
#pragma unroll
            for (int half = 0; half < 2; half++) {
                int row = m0 + wm * 64 + mi * 16 + g + half * 8;
                int col = n0 + wn * 32 + ni * 8 + 2 * qr;
                float v0 = c[mi][ni][half * 2 + 0];
                float v1 = c[mi][ni][half * 2 + 1];
                if (mode == 3) {
                    v0 += bias[col];
                    v1 += bias[col + 1];
                    *(float2*)&C[(size_t)row * 1024 + col] = make_float2(v0, v1);
                } else {
                    // store tf32-rounded so attn needs no CVT
                    v0 = __uint_as_float(f2tf(v0));
                    v1 = __uint_as_float(f2tf(v1));
                    int b_ = row >> 11, s_ = row & (Sn - 1);
                    int h_ = col >> 6, dk = col & 63;
                    size_t o = (((size_t)(b_ * Hn + h_) * Sn) + s_) * DKn + dk;
                    *(float2*)&C[o] = make_float2(v0, v1);
                }
            }
}

// ---------------------------------------------------------------------------
// Attention: 8 warps (4q x 2k), warp tile 16q x 32k over a 64-q block tile.
// Q/K/V arrive pre-rounded: fragment loads are raw bit reinterprets (no CVT).
// ---------------------------------------------------------------------------
#define KROW 68
#define VROW 72
#define KTILE (64 * KROW)
#define VTILE (64 * VROW)
#define ATTN_SMEM ((2 * KTILE + 2 * VTILE) * 4)

__global__ __launch_bounds__(256)
void attn_tc(const float* __restrict__ bias_table, float* __restrict__ attn_out)
{
    extern __shared__ float sm[];
    float* KsF = sm;                 // [2][KTILE]
    float* VsF = sm + 2 * KTILE;     // [2][VTILE]
    __shared__ float bias_s[2][128];
    __shared__ float rs[2][64];
    __shared__ float rinv_s[64];

    const int tid = threadIdx.x;
    const int w = tid >> 5, lane = tid & 31, g = lane >> 2, qr = lane & 3;
    const int wq = w >> 1, wk = w & 1;
    const int qt = blockIdx.x, bh = blockIdx.y;
    const int b_ = bh >> 4, h_ = bh & 15;
    const int q0 = qt * 64;
    const int qlo = wq * 16 + g;

    const float* Qb = g_Q + (size_t)bh * Sn * DKn;
    const float* Kb = g_K + (size_t)bh * Sn * DKn;
    const float* Vb = g_V + (size_t)bh * Sn * DKn;
    const float* bias_base = bias_table + (size_t)(q0 + MAXSEQ - 1 - 63) * Hn + h_;

    // Q fragments (already tf32-valued)
    unsigned qa[8][4];
    {
        const float* r0 = Qb + (size_t)(q0 + qlo) * DKn;
        const float* r1 = r0 + 8 * DKn;
#pragma unroll
        for (int kc = 0; kc < 8; kc++) {
            qa[kc][0] = __float_as_uint(r0[kc * 8 + qr]);
            qa[kc][1] = __float_as_uint(r1[kc * 8 + qr]);
            qa[kc][2] = __float_as_uint(r0[kc * 8 + qr + 4]);
            qa[kc][3] = __float_as_uint(r1[kc * 8 + qr + 4]);
        }
    }

    const int src0 = (lane & 28) | (qr >> 1);
    const int src1 = src0 + 2;
    const bool odd = (qr & 1);

    float ctx[8][4] = {};
    float psum[2] = {};

    // Prologue: prefetch tile 0
    {
#pragma unroll
        for (int it = 0; it < 4; it++) {
            int idx = tid + it * 256;            // 1024 float4 units
            int row = idx >> 4, cc = idx & 15;
            cp_async16(&KsF[row * KROW + cc * 4], &Kb[(size_t)row * DKn + cc * 4]);
            cp_async16(&VsF[row * VROW + cc * 4], &Vb[(size_t)row * DKn + cc * 4]);
        }
        if (tid < 127) cp_async4(&bias_s[0][tid], bias_base + (size_t)tid * Hn);
        cp_commit();
    }

    // ---------------- Pass A ----------------
    for (int kt = 0; kt < 32; kt++) {
        const int st = kt & 1;
        cp_wait<0>();
        __syncthreads();

        if (kt + 1 < 32) {
            const int k1 = (kt + 1) * 64;
            const float* Kn = Kb + (size_t)k1 * DKn;
            const float* Vn = Vb + (size_t)k1 * DKn;
            float* Kd = KsF + (st ^ 1) * KTILE;
            float* Vd = VsF + (st ^ 1) * VTILE;
#pragma unroll
            for (int it = 0; it < 4; it++) {
                int idx = tid + it * 256;
                int row = idx >> 4, cc = idx & 15;
                cp_async16(&Kd[row * KROW + cc * 4], &Kn[(size_t)row * DKn + cc * 4]);
                cp_async16(&Vd[row * VROW + cc * 4], &Vn[(size_t)row * DKn + cc * 4]);
            }
            if (tid < 127)
                cp_async4(&bias_s[st ^ 1][tid], bias_base + (size_t)(tid - k1) * Hn);
            cp_commit();
        }

        const float* Kt = KsF + st * KTILE;
        const float* Vt = VsF + st * VTILE;

        // S = Q K^T : 16q x 32k per warp
        float sacc[4][4] = {};
#pragma unroll
        for (int kc = 0; kc < 8; kc++) {
#pragma unroll
            for (int ni = 0; ni < 4; ni++) {
                int col = wk * 32 + ni * 8 + g;
                unsigned b0 = __float_as_uint(Kt[col * KROW + kc * 8 + qr]);
                unsigned b1 = __float_as_uint(Kt[col * KROW + kc * 8 + qr + 4]);
                mma_tf32(sacc[ni], qa[kc], b0, b1);
            }
        }

        // exp + bias, psum, convert to A-frags (only CVTs left: 16 for P)
        unsigned pA[4][4];
#pragma unroll
        for (int ni = 0; ni < 4; ni++) {
            int kj = wk * 32 + ni * 8 + 2 * qr;
            int idx0 = qlo - kj + 63;
            float p0 = __expf(sacc[ni][0] * 0.125f + bias_s[st][idx0]);
            float p1 = __expf(sacc[ni][1] * 0.125f + bias_s[st][idx0 - 1]);
            float p2 = __expf(sacc[ni][2] * 0.125f + bias_s[st][idx0 + 8]);
            float p3 = __expf(sacc[ni][3] * 0.125f + bias_s[st][idx0 + 7]);
            psum[0] += p0 + p1;
            psum[1] += p2 + p3;
            float u0 = __shfl_sync(0xffffffffu, p0, src0);
            float u1 = __shfl_sync(0xffffffffu, p1, src0);
            pA[ni][0] = f2tf(odd ? u1 : u0);
            float u2 = __shfl_sync(0xffffffffu, p2, src0);
            float u3 = __shfl_sync(0xffffffffu, p3, src0);
            pA[ni][1] = f2tf(odd ? u3 : u2);
            float u4 = __shfl_sync(0xffffffffu, p0, src1);
            float u5 = __shfl_sync(0xffffffffu, p1, src1);
            pA[ni][2] = f2tf(odd ? u5 : u4);
            float u6 = __shfl_sync(0xffffffffu, p2, src1);
            float u7 = __shfl_sync(0xffffffffu, p3, src1);
            pA[ni][3] = f2tf(odd ? u7 : u6);
        }

        // ctx += P @ V
#pragma unroll
        for (int kc2 = 0; kc2 < 4; kc2++) {
            int krow = wk * 32 + kc2 * 8 + qr;
#pragma unroll
            for (int n2 = 0; n2 < 8; n2++) {
                unsigned b0 = __float_as_uint(Vt[krow * VROW + n2 * 8 + g]);
                unsigned b1 = __float_as_uint(Vt[(krow + 4) * VROW + n2 * 8 + g]);
                mma_tf32(ctx[n2], pA[kc2], b0, b1);
            }
        }
    }

    // Rowsums per wk half
#pragma unroll
    for (int h2 = 0; h2 < 2; h2++) {
        float v = psum[h2];
        v += __shfl_xor_sync(0xffffffffu, v, 1);
        v += __shfl_xor_sync(0xffffffffu, v, 2);
        if (qr == 0) rs[wk][wq * 16 + h2 * 8 + g] = v;
    }
    __syncthreads();

    float* Kf = KsF;   // scratch
    if (wk == 1) {
#pragma unroll
        for (int n2 = 0; n2 < 8; n2++) {
            *(float2*)&Kf[qlo * KROW + n2 * 8 + 2 * qr] =
                make_float2(ctx[n2][0], ctx[n2][1]);
            *(float2*)&Kf[(qlo + 8) * KROW + n2 * 8 + 2 * qr] =
                make_float2(ctx[n2][2], ctx[n2][3]);
        }
    }
    if (tid < 64) rinv_s[tid] = 1.0f / (rs[0][tid] + rs[1][tid]);
    __syncthreads();

    if (wk == 0) {
        float r0 = rinv_s[qlo], r1 = rinv_s[qlo + 8];
#pragma unroll
        for (int n2 = 0; n2 < 8; n2++) {
            float2 o0 = *(float2*)&Kf[qlo * KROW + n2 * 8 + 2 * qr];
            float2 o1 = *(float2*)&Kf[(qlo + 8) * KROW + n2 * 8 + 2 * qr];
            int col = h_ * 64 + n2 * 8 + 2 * qr;
            size_t a0 = ((size_t)(b_ * Sn + q0 + qlo)) * Dn + col;
            // store tf32-rounded: mode-3 gemm consumes without CVT
            *(float2*)&g_CTX[a0] = make_float2(
                __uint_as_float(f2tf((ctx[n2][0] + o0.x) * r0)),
                __uint_as_float(f2tf((ctx[n2][1] + o0.y) * r0)));
            *(float2*)&g_CTX[a0 + 8 * Dn] = make_float2(
                __uint_as_float(f2tf((ctx[n2][2] + o1.x) * r1)),
                __uint_as_float(f2tf((ctx[n2][3] + o1.y) * r1)));
        }
    }

    if (!attn_out) return;

    const float rv0 = rinv_s[qlo];
    const float rv1 = rinv_s[qlo + 8];
    __syncthreads();

    // ---------------- Pass B ----------------
    {
#pragma unroll
        for (int it = 0; it < 4; it++) {
            int idx = tid + it * 256;
            int row = idx >> 4, cc = idx & 15;
            cp_async16(&KsF[row * KROW + cc * 4], &Kb[(size_t)row * DKn + cc * 4]);
        }
        if (tid < 127) cp_async4(&bias_s[0][tid], bias_base + (size_t)tid * Hn);
        cp_commit();
    }

    for (int kt = 0; kt < 32; kt++) {
        const int st = kt & 1;
        const int k0 = kt * 64;
        cp_wait<0>();
        __syncthreads();

        if (kt + 1 < 32) {
            const int k1 = (kt + 1) * 64;
            const float* Kn = Kb + (size_t)k1 * DKn;
            float* Kd = KsF + (st ^ 1) * KTILE;
#pragma unroll
            for (int it = 0; it < 4; it++) {
                int idx = tid + it * 256;
                int row = idx >> 4, cc = idx & 15;
                cp_async16(&Kd[row * KROW + cc * 4], &Kn[(size_t)row * DKn + cc * 4]);
            }
            if (tid < 127)
                cp_async4(&bias_s[st ^ 1][tid], bias_base + (size_t)(tid - k1) * Hn);
            cp_commit();
        }

        const float* Kt = KsF + st * KTILE;

        float sacc[4][4] = {};
#pragma unroll
        for (int kc = 0; kc < 8; kc++) {
#pragma unroll
            for (int ni = 0; ni < 4; ni++) {
                int col = wk * 32 + ni * 8 + g;
                unsigned b0 = __float_as_uint(Kt[col * KROW + kc * 8 + qr]);
                unsigned b1 = __float_as_uint(Kt[col * KROW + kc * 8 + qr + 4]);
                mma_tf32(sacc[ni], qa[kc], b0, b1);
            }
        }

        size_t rbase0 = ((size_t)(bh * Sn + q0 + qlo)) * Sn + k0;
        size_t rbase1 = rbase0 + 8 * (size_t)Sn;
#pragma unroll
        for (int ni = 0; ni < 4; ni++) {
            int kj = wk * 32 + ni * 8 + 2 * qr;
            int idx0 = qlo - kj + 63;
            float p0 = __expf(sacc[ni][0] * 0.125f + bias_s[st][idx0]) * rv0;
            float p1 = __expf(sacc[ni][1] * 0.125f + bias_s[st][idx0 - 1]) * rv0;
            float p2 = __expf(sacc[ni][2] * 0.125f + bias_s[st][idx0 + 8]) * rv1;
            float p3 = __expf(sacc[ni][3] * 0.125f + bias_s[st][idx0 + 7]) * rv1;
            *(float2*)&attn_out[rbase0 + kj] = make_float2(p0, p1);
            *(float2*)&attn_out[rbase1 + kj] = make_float2(p2, p3);
        }
    }
}

// ---------------------------------------------------------------------------
extern "C" void kernel_launch(void* const* d_in, const int* in_sizes, int n_in,
                              void* d_out, int out_size)
{
    const float* query      = (const float*)d_in[0];
    const float* key        = (const float*)d_in[1];
    const float* value      = (const float*)d_in[2];
    const float* Wq         = (const float*)d_in[3];
    const float* Wk         = (const float*)d_in[4];
    const float* Wv         = (const float*)d_in[5];
    const float* Wo         = (const float*)d_in[6];
    const float* bo         = (const float*)d_in[7];
    const float* bias_table = (const float*)d_in[8];

    float* out = (float*)d_out;
    const bool has_attn = (long long)out_size >= (OUT_ELEMS + ATTN_ELEMS);
    float* attn = has_attn ? out + OUT_ELEMS : nullptr;

    cudaFuncSetAttribute(attn_tc, cudaFuncAttributeMaxDynamicSharedMemorySize,
                         ATTN_SMEM);

    // Pre-round inputs to tf32 (scratch)
    float *rq, *rk, *rv, *wq_, *wk_, *wv_, *wo_;
    cudaGetSymbolAddress((void**)&rq, g_RQ);
    cudaGetSymbolAddress((void**)&rk, g_RK);
    cudaGetSymbolAddress((void**)&rv, g_RV);
    cudaGetSymbolAddress((void**)&wq_, g_WQ);
    cudaGetSymbolAddress((void**)&wk_, g_WK);
    cudaGetSymbolAddress((void**)&wv_, g_WV);
    cudaGetSymbolAddress((void**)&wo_, g_WO);

    const int N4a = (Bn * Sn * Dn) / 4;   // 1,048,576
    const int N4w = (Dn * Dn) / 4;        // 262,144
    round_kernel<<<N4a / 256, 256>>>(query, rq, N4a);
    round_kernel<<<N4a / 256, 256>>>(key,   rk, N4a);
    round_kernel<<<N4a / 256, 256>>>(value, rv, N4a);
    round_kernel<<<N4w / 256, 256>>>(Wq, wq_, N4w);
    round_kernel<<<N4w / 256, 256>>>(Wk, wk_, N4w);
    round_kernel<<<N4w / 256, 256>>>(Wv, wv_, N4w);
    round_kernel<<<N4w / 256, 256>>>(Wo, wo_, N4w);

    float* gctx;
    cudaGetSymbolAddress((void**)&gctx, g_CTX);

    dim3 gproj(1024 / 128, MROWS / 128);   // 8 x 32
    gemm_tc<<<gproj, 256>>>(rq, wq_, nullptr, nullptr, 0);
    gemm_tc<<<gproj, 256>>>(rk, wk_, nullptr, nullptr, 1);
    gemm_tc<<<gproj, 256>>>(rv, wv_, nullptr, nullptr, 2);

    dim3 gattn(Sn / 64, Bn * Hn);          // 32 x 32
    attn_tc<<<gattn, 256, ATTN_SMEM>>>(bias_table, attn);

    gemm_tc<<<gproj, 256>>>(gctx, wo_, bo, out, 3);
}

// round 10
// speedup vs baseline: 2.8931x; 1.0421x over previous
#include <cuda_runtime.h>

#define Bn 2
#define Sn 2048
#define Dn 1024
#define Hn 16
#define DKn 64
#define MAXSEQ 2048
#define MROWS (Bn * Sn)
#define OUT_ELEMS (MROWS * Dn)
#define ATTN_ELEMS ((long long)Bn * Hn * Sn * Sn)

__device__ float g_Q[Bn * Sn * Dn];
__device__ float g_K[Bn * Sn * Dn];
__device__ float g_V[Bn * Sn * Dn];
__device__ float g_CTX[Bn * Sn * Dn];
__device__ float g_RINV[Bn * Hn * Sn];
// pre-rounded (tf32-valued fp32) copies of inputs
__device__ float g_RQ[Bn * Sn * Dn];
__device__ float g_RK[Bn * Sn * Dn];
__device__ float g_RV[Bn * Sn * Dn];
__device__ float g_WQ[Dn * Dn];
__device__ float g_WK[Dn * Dn];
__device__ float g_WV[Dn * Dn];
__device__ float g_WO[Dn * Dn];

__device__ __forceinline__ unsigned f2tf(float x) {
    unsigned u;
    asm("cvt.rna.tf32.f32 %0, %1;" : "=r"(u) : "f"(x));
    return u;
}

__device__ __forceinline__ void mma_tf32(float c[4], const unsigned a[4],
                                         unsigned b0, unsigned b1) {
    asm volatile(
        "mma.sync.aligned.m16n8k8.row.col.f32.tf32.tf32.f32 "
        "{%0,%1,%2,%3}, {%4,%5,%6,%7}, {%8,%9}, {%0,%1,%2,%3};"
        : "+f"(c[0]), "+f"(c[1]), "+f"(c[2]), "+f"(c[3])
        : "r"(a[0]), "r"(a[1]), "r"(a[2]), "r"(a[3]), "r"(b0), "r"(b1));
}

__device__ __forceinline__ void cp_async16(void* dst, const void* src) {
    unsigned s = (unsigned)__cvta_generic_to_shared(dst);
    asm volatile("cp.async.cg.shared.global [%0], [%1], 16;" :: "r"(s), "l"(src));
}
__device__ __forceinline__ void cp_async4(void* dst, const void* src) {
    unsigned s = (unsigned)__cvta_generic_to_shared(dst);
    asm volatile("cp.async.ca.shared.global [%0], [%1], 4;" :: "r"(s), "l"(src));
}
__device__ __forceinline__ void cp_commit() {
    asm volatile("cp.async.commit_group;");
}
template <int N>
__device__ __forceinline__ void cp_wait() {
    asm volatile("cp.async.wait_group %0;" :: "n"(N));
}

// ---------------------------------------------------------------------------
// Fused tf32 pre-rounding of all 7 inputs (single launch).
// ---------------------------------------------------------------------------
#define N4A ((Bn * Sn * Dn) / 4)   // 1,048,576
#define N4W ((Dn * Dn) / 4)        // 262,144

__global__ __launch_bounds__(256)
void round_all(const float* __restrict__ q, const float* __restrict__ k,
               const float* __restrict__ v, const float* __restrict__ wq,
               const float* __restrict__ wk, const float* __restrict__ wv,
               const float* __restrict__ wo)
{
    int i = blockIdx.x * 256 + threadIdx.x;
    const float* s;
    float* d;
    int j = i;
    if (j < N4A)                 { s = q;  d = g_RQ; }
    else if ((j -= N4A) < N4A)   { s = k;  d = g_RK; }
    else if ((j -= N4A) < N4A)   { s = v;  d = g_RV; }
    else if ((j -= N4A) < N4W)   { s = wq; d = g_WQ; }
    else if ((j -= N4W) < N4W)   { s = wk; d = g_WK; }
    else if ((j -= N4W) < N4W)   { s = wv; d = g_WV; }
    else                         { j -= N4W; s = wo; d = g_WO; }
    float4 x = ((const float4*)s)[j];
    x.x = __uint_as_float(f2tf(x.x));
    x.y = __uint_as_float(f2tf(x.y));
    x.z = __uint_as_float(f2tf(x.z));
    x.w = __uint_as_float(f2tf(x.w));
    ((float4*)d)[j] = x;
}

// ---------------------------------------------------------------------------
// Projection GEMM (pre-rounded inputs; no CVT in hot loop).
// ---------------------------------------------------------------------------
#define GP 20

__global__ __launch_bounds__(256)
void gemm_tc(const float* __restrict__ A, const float* __restrict__ W,
             const float* __restrict__ bias, float* __restrict__ Cext, int mode)
{
    __shared__ float As[2][128 * GP];
    __shared__ float Ws[2][128 * GP];

    float* C = (mode == 0) ? g_Q : (mode == 1) ? g_K : (mode == 2) ? g_V : Cext;

    const int tid = threadIdx.x;
    const int w = tid >> 5, lane = tid & 31, g = lane >> 2, qr = lane & 3;
    const int wm = w >> 2, wn = w & 3;
    const int m0 = blockIdx.y * 128, n0 = blockIdx.x * 128;
    const int row_f = tid >> 2, c4 = tid & 3;

    float c[4][4][4] = {};

#pragma unroll
    for (int it = 0; it < 2; it++) {
        int rr = row_f + it * 64;
        cp_async16(&As[0][rr * GP + c4 * 4], &A[(size_t)(m0 + rr) * 1024 + c4 * 4]);
        cp_async16(&Ws[0][rr * GP + c4 * 4], &W[(size_t)(n0 + rr) * 1024 + c4 * 4]);
    }
    cp_commit();

    int st = 0;
    for (int k0 = 0; k0 < 1024; k0 += 16) {
        if (k0 + 16 < 1024) {
#pragma unroll
            for (int it = 0; it < 2; it++) {
                int rr = row_f + it * 64;
                cp_async16(&As[st ^ 1][rr * GP + c4 * 4],
                           &A[(size_t)(m0 + rr) * 1024 + k0 + 16 + c4 * 4]);
                cp_async16(&Ws[st ^ 1][rr * GP + c4 * 4],
                           &W[(size_t)(n0 + rr) * 1024 + k0 + 16 + c4 * 4]);
            }
            cp_commit();
            cp_wait<1>();
        } else {
            cp_wait<0>();
        }
        __syncthreads();

#pragma unroll
        for (int kk = 0; kk < 16; kk += 8) {
            unsigned a[4][4], b[4][2];
#pragma unroll
            for (int mi = 0; mi < 4; mi++) {
                int r = wm * 64 + mi * 16 + g;
                a[mi][0] = __float_as_uint(As[st][r * GP + kk + qr]);
                a[mi][1] = __float_as_uint(As[st][(r + 8) * GP + kk + qr]);
                a[mi][2] = __float_as_uint(As[st][r * GP + kk + qr + 4]);
                a[mi][3] = __float_as_uint(As[st][(r + 8) * GP + kk + qr + 4]);
            }
#pragma unroll
            for (int ni = 0; ni < 4; ni++) {
                int col = wn * 32 + ni * 8 + g;
                b[ni][0] = __float_as_uint(Ws[st][col * GP + kk + qr]);
                b[ni][1] = __float_as_uint(Ws[st][col * GP + kk + qr + 4]);
            }
#pragma unroll
            for (int mi = 0; mi < 4; mi++)
#pragma unroll
                for (int ni = 0; ni < 4; ni++)
                    mma_tf32(c[mi][ni], a[mi], b[ni][0], b[ni][1]);
        }
        __syncthreads();
        st ^= 1;
    }

#pragma unroll
    for (int mi = 0; mi < 4; mi++)
#pragma unroll
        for (int ni = 0; ni < 4; ni++)
#pragma unroll
            for (int half = 0; half < 2; half++) {
                int row = m0 + wm * 64 + mi * 16 + g + half * 8;
                int col = n0 + wn * 32 + ni * 8 + 2 * qr;
                float v0 = c[mi][ni][half * 2 + 0];
                float v1 = c[mi][ni][half * 2 + 1];
                if (mode == 3) {
                    v0 += bias[col];
                    v1 += bias[col + 1];
                    *(float2*)&C[(size_t)row * 1024 + col] = make_float2(v0, v1);
                } else {
                    v0 = __uint_as_float(f2tf(v0));
                    v1 = __uint_as_float(f2tf(v1));
                    int b_ = row >> 11, s_ = row & (Sn - 1);
                    int h_ = col >> 6, dk = col & 63;
                    size_t o = (((size_t)(b_ * Hn + h_) * Sn) + s_) * DKn + dk;
                    *(float2*)&C[o] = make_float2(v0, v1);
                }
            }
}

// ---------------------------------------------------------------------------
// attn_a: ctx + rowsums only. Writes scaled ctx to g_CTX (tf32-rounded) and
// 1/rowsum to g_RINV.
// ---------------------------------------------------------------------------
#define KROW 68
#define VROW 72
#define KTILE (64 * KROW)
#define VTILE (64 * VROW)
#define A_SMEM ((2 * KTILE + 2 * VTILE) * 4)
#define B_SMEM ((2 * KTILE) * 4)

__global__ __launch_bounds__(256)
void attn_a(const float* __restrict__ bias_table)
{
    extern __shared__ float sm[];
    float* KsF = sm;                 // [2][KTILE]
    float* VsF = sm + 2 * KTILE;     // [2][VTILE]
    __shared__ float bias_s[2][128];
    __shared__ float rs[2][64];
    __shared__ float rinv_s[64];

    const int tid = threadIdx.x;
    const int w = tid >> 5, lane = tid & 31, g = lane >> 2, qr = lane & 3;
    const int wq = w >> 1, wk = w & 1;
    const int qt = blockIdx.x, bh = blockIdx.y;
    const int b_ = bh >> 4, h_ = bh & 15;
    const int q0 = qt * 64;
    const int qlo = wq * 16 + g;

    const float* Qb = g_Q + (size_t)bh * Sn * DKn;
    const float* Kb = g_K + (size_t)bh * Sn * DKn;
    const float* Vb = g_V + (size_t)bh * Sn * DKn;
    const float* bias_base = bias_table + (size_t)(q0 + MAXSEQ - 1 - 63) * Hn + h_;

    unsigned qa[8][4];
    {
        const float* r0 = Qb + (size_t)(q0 + qlo) * DKn;
        const float* r1 = r0 + 8 * DKn;
#pragma unroll
        for (int kc = 0; kc < 8; kc++) {
            qa[kc][0] = __float_as_uint(r0[kc * 8 + qr]);
            qa[kc][1] = __float_as_uint(r1[kc * 8 + qr]);
            qa[kc][2] = __float_as_uint(r0[kc * 8 + qr + 4]);
            qa[kc][3] = __float_as_uint(r1[kc * 8 + qr + 4]);
        }
    }

    const int src0 = (lane & 28) | (qr >> 1);
    const int src1 = src0 + 2;
    const bool odd = (qr & 1);

    float ctx[8][4] = {};
    float psum[2] = {};

    {
#pragma unroll
        for (int it = 0; it < 4; it++) {
            int idx = tid + it * 256;
            int row = idx >> 4, cc = idx & 15;
            cp_async16(&KsF[row * KROW + cc * 4], &Kb[(size_t)row * DKn + cc * 4]);
            cp_async16(&VsF[row * VROW + cc * 4], &Vb[(size_t)row * DKn + cc * 4]);
        }
        if (tid < 127) cp_async4(&bias_s[0][tid], bias_base + (size_t)tid * Hn);
        cp_commit();
    }

    for (int kt = 0; kt < 32; kt++) {
        const int st = kt & 1;
        cp_wait<0>();
        __syncthreads();

        if (kt + 1 < 32) {
            const int k1 = (kt + 1) * 64;
            const float* Kn = Kb + (size_t)k1 * DKn;
            const float* Vn = Vb + (size_t)k1 * DKn;
            float* Kd = KsF + (st ^ 1) * KTILE;
            float* Vd = VsF + (st ^ 1) * VTILE;
#pragma unroll
            for (int it = 0; it < 4; it++) {
                int idx = tid + it * 256;
                int row = idx >> 4, cc = idx & 15;
                cp_async16(&Kd[row * KROW + cc * 4], &Kn[(size_t)row * DKn + cc * 4]);
                cp_async16(&Vd[row * VROW + cc * 4], &Vn[(size_t)row * DKn + cc * 4]);
            }
            if (tid < 127)
                cp_async4(&bias_s[st ^ 1][tid], bias_base + (size_t)(tid - k1) * Hn);
            cp_commit();
        }

        const float* Kt = KsF + st * KTILE;
        const float* Vt = VsF + st * VTILE;

        float sacc[4][4] = {};
#pragma unroll
        for (int kc = 0; kc < 8; kc++) {
#pragma unroll
            for (int ni = 0; ni < 4; ni++) {
                int col = wk * 32 + ni * 8 + g;
                unsigned b0 = __float_as_uint(Kt[col * KROW + kc * 8 + qr]);
                unsigned b1 = __float_as_uint(Kt[col * KROW + kc * 8 + qr + 4]);
                mma_tf32(sacc[ni], qa[kc], b0, b1);
            }
        }

        unsigned pA[4][4];
#pragma unroll
        for (int ni = 0; ni < 4; ni++) {
            int kj = wk * 32 + ni * 8 + 2 * qr;
            int idx0 = qlo - kj + 63;
            float p0 = __expf(sacc[ni][0] * 0.125f + bias_s[st][idx0]);
            float p1 = __expf(sacc[ni][1] * 0.125f + bias_s[st][idx0 - 1]);
            float p2 = __expf(sacc[ni][2] * 0.125f + bias_s[st][idx0 + 8]);
            float p3 = __expf(sacc[ni][3] * 0.125f + bias_s[st][idx0 + 7]);
            psum[0] += p0 + p1;
            psum[1] += p2 + p3;
            float u0 = __shfl_sync(0xffffffffu, p0, src0);
            float u1 = __shfl_sync(0xffffffffu, p1, src0);
            pA[ni][0] = f2tf(odd ? u1 : u0);
            float u2 = __shfl_sync(0xffffffffu, p2, src0);
            float u3 = __shfl_sync(0xffffffffu, p3, src0);
            pA[ni][1] = f2tf(odd ? u3 : u2);
            float u4 = __shfl_sync(0xffffffffu, p0, src1);
            float u5 = __shfl_sync(0xffffffffu, p1, src1);
            pA[ni][2] = f2tf(odd ? u5 : u4);
            float u6 = __shfl_sync(0xffffffffu, p2, src1);
            float u7 = __shfl_sync(0xffffffffu, p3, src1);
            pA[ni][3] = f2tf(odd ? u7 : u6);
        }

#pragma unroll
        for (int kc2 = 0; kc2 < 4; kc2++) {
            int krow = wk * 32 + kc2 * 8 + qr;
#pragma unroll
            for (int n2 = 0; n2 < 8; n2++) {
                unsigned b0 = __float_as_uint(Vt[krow * VROW + n2 * 8 + g]);
                unsigned b1 = __float_as_uint(Vt[(krow + 4) * VROW + n2 * 8 + g]);
                mma_tf32(ctx[n2], pA[kc2], b0, b1);
            }
        }
    }

#pragma unroll
    for (int h2 = 0; h2 < 2; h2++) {
        float v = psum[h2];
        v += __shfl_xor_sync(0xffffffffu, v, 1);
        v += __shfl_xor_sync(0xffffffffu, v, 2);
        if (qr == 0) rs[wk][wq * 16 + h2 * 8 + g] = v;
    }
    __syncthreads();

    float* Kf = KsF;
    if (wk == 1) {
#pragma unroll
        for (int n2 = 0; n2 < 8; n2++) {
            *(float2*)&Kf[qlo * KROW + n2 * 8 + 2 * qr] =
                make_float2(ctx[n2][0], ctx[n2][1]);
            *(float2*)&Kf[(qlo + 8) * KROW + n2 * 8 + 2 * qr] =
                make_float2(ctx[n2][2], ctx[n2][3]);
        }
    }
    if (tid < 64) {
        float r = 1.0f / (rs[0][tid] + rs[1][tid]);
        rinv_s[tid] = r;
        g_RINV[(size_t)bh * Sn + q0 + tid] = r;
    }
    __syncthreads();

    if (wk == 0) {
        float r0 = rinv_s[qlo], r1 = rinv_s[qlo + 8];
#pragma unroll
        for (int n2 = 0; n2 < 8; n2++) {
            float2 o0 = *(float2*)&Kf[qlo * KROW + n2 * 8 + 2 * qr];
            float2 o1 = *(float2*)&Kf[(qlo + 8) * KROW + n2 * 8 + 2 * qr];
            int col = h_ * 64 + n2 * 8 + 2 * qr;
            size_t a0 = ((size_t)(b_ * Sn + q0 + qlo)) * Dn + col;
            *(float2*)&g_CTX[a0] = make_float2(
                __uint_as_float(f2tf((ctx[n2][0] + o0.x) * r0)),
                __uint_as_float(f2tf((ctx[n2][1] + o0.y) * r0)));
            *(float2*)&g_CTX[a0 + 8 * Dn] = make_float2(
                __uint_as_float(f2tf((ctx[n2][2] + o1.x) * r1)),
                __uint_as_float(f2tf((ctx[n2][3] + o1.y) * r1)));
        }
    }
}

// ---------------------------------------------------------------------------
// attn_b: recompute S, write normalized attn. No V smem, no ctx registers ->
// high occupancy for the store-bound phase.
// ---------------------------------------------------------------------------
__global__ __launch_bounds__(256)
void attn_b(const float* __restrict__ bias_table, float* __restrict__ attn_out)
{
    extern __shared__ float sm[];
    float* KsF = sm;                 // [2][KTILE]
    __shared__ float bias_s[2][128];

    const int tid = threadIdx.x;
    const int w = tid >> 5, lane = tid & 31, g = lane >> 2, qr = lane & 3;
    const int wq = w >> 1, wk = w & 1;
    const int qt = blockIdx.x, bh = blockIdx.y;
    const int h_ = bh & 15;
    const int q0 = qt * 64;
    const int qlo = wq * 16 + g;

    const float* Qb = g_Q + (size_t)bh * Sn * DKn;
    const float* Kb = g_K + (size_t)bh * Sn * DKn;
    const float* bias_base = bias_table + (size_t)(q0 + MAXSEQ - 1 - 63) * Hn + h_;

    unsigned qa[8][4];
    {
        const float* r0 = Qb + (size_t)(q0 + qlo) * DKn;
        const float* r1 = r0 + 8 * DKn;
#pragma unroll
        for (int kc = 0; kc < 8; kc++) {
            qa[kc][0] = __float_as_uint(r0[kc * 8 + qr]);
            qa[kc][1] = __float_as_uint(r1[kc * 8 + qr]);
            qa[kc][2] = __float_as_uint(r0[kc * 8 + qr + 4]);
            qa[kc][3] = __float_as_uint(r1[kc * 8 + qr + 4]);
        }
    }

    const float rv0 = g_RINV[(size_t)bh * Sn + q0 + qlo];
    const float rv1 = g_RINV[(size_t)bh * Sn + q0 + qlo + 8];

    {
#pragma unroll
        for (int it = 0; it < 4; it++) {
            int idx = tid + it * 256;
            int row = idx >> 4, cc = idx & 15;
            cp_async16(&KsF[row * KROW + cc * 4], &Kb[(size_t)row * DKn + cc * 4]);
        }
        if (tid < 127) cp_async4(&bias_s[0][tid], bias_base + (size_t)tid * Hn);
        cp_commit();
    }

    for (int kt = 0; kt < 32; kt++) {
        const int st = kt & 1;
        const int k0 = kt * 64;
        cp_wait<0>();
        __syncthreads();

        if (kt + 1 < 32) {
            const int k1 = (kt + 1) * 64;
            const float* Kn = Kb + (size_t)k1 * DKn;
            float* Kd = KsF + (st ^ 1) * KTILE;
#pragma unroll
            for (int it = 0; it < 4; it++) {
                int idx = tid + it * 256;
                int row = idx >> 4, cc = idx & 15;
                cp_async16(&Kd[row * KROW + cc * 4], &Kn[(size_t)row * DKn + cc * 4]);
            }
            if (tid < 127)
                cp_async4(&bias_s[st ^ 1][tid], bias_base + (size_t)(tid - k1) * Hn);
            cp_commit();
        }

        const float* Kt = KsF + st * KTILE;

        float sacc[4][4] = {};
#pragma unroll
        for (int kc = 0; kc < 8; kc++) {
#pragma unroll
            for (int ni = 0; ni < 4; ni++) {
                int col = wk * 32 + ni * 8 + g;
                unsigned b0 = __float_as_uint(Kt[col * KROW + kc * 8 + qr]);
                unsigned b1 = __float_as_uint(Kt[col * KROW + kc * 8 + qr + 4]);
                mma_tf32(sacc[ni], qa[kc], b0, b1);
            }
        }

        size_t rbase0 = ((size_t)(bh * Sn + q0 + qlo)) * Sn + k0;
        size_t rbase1 = rbase0 + 8 * (size_t)Sn;
#pragma unroll
        for (int ni = 0; ni < 4; ni++) {
            int kj = wk * 32 + ni * 8 + 2 * qr;
            int idx0 = qlo - kj + 63;
            float p0 = __expf(sacc[ni][0] * 0.125f + bias_s[st][idx0]) * rv0;
            float p1 = __expf(sacc[ni][1] * 0.125f + bias_s[st][idx0 - 1]) * rv0;
            float p2 = __expf(sacc[ni][2] * 0.125f + bias_s[st][idx0 + 8]) * rv1;
            float p3 = __expf(sacc[ni][3] * 0.125f + bias_s[st][idx0 + 7]) * rv1;
            *(float2*)&attn_out[rbase0 + kj] = make_float2(p0, p1);
            *(float2*)&attn_out[rbase1 + kj] = make_float2(p2, p3);
        }
    }
}

// ---------------------------------------------------------------------------
extern "C" void kernel_launch(void* const* d_in, const int* in_sizes, int n_in,
                              void* d_out, int out_size)
{
    const float* query      = (const float*)d_in[0];
    const float* key        = (const float*)d_in[1];
    const float* value      = (const float*)d_in[2];
    const float* Wq         = (const float*)d_in[3];
    const float* Wk         = (const float*)d_in[4];
    const float* Wv         = (const float*)d_in[5];
    const float* Wo         = (const float*)d_in[6];
    const float* bo         = (const float*)d_in[7];
    const float* bias_table = (const float*)d_in[8];

    float* out = (float*)d_out;
    const bool has_attn = (long long)out_size >= (OUT_ELEMS + ATTN_ELEMS);
    float* attn = has_attn ? out + OUT_ELEMS : nullptr;

    cudaFuncSetAttribute(attn_a, cudaFuncAttributeMaxDynamicSharedMemorySize, A_SMEM);
    cudaFuncSetAttribute(attn_b, cudaFuncAttributeMaxDynamicSharedMemorySize, B_SMEM);

    float *rq, *rk, *rv, *wq_, *wk_, *wv_, *wo_, *gctx;
    cudaGetSymbolAddress((void**)&rq, g_RQ);
    cudaGetSymbolAddress((void**)&rk, g_RK);
    cudaGetSymbolAddress((void**)&rv, g_RV);
    cudaGetSymbolAddress((void**)&wq_, g_WQ);
    cudaGetSymbolAddress((void**)&wk_, g_WK);
    cudaGetSymbolAddress((void**)&wv_, g_WV);
    cudaGetSymbolAddress((void**)&wo_, g_WO);
    cudaGetSymbolAddress((void**)&gctx, g_CTX);

    const int total4 = 3 * N4A + 4 * N4W;            // 4,194,304
    round_all<<<total4 / 256, 256>>>(query, key, value, Wq, Wk, Wv, Wo);

    dim3 gproj(1024 / 128, MROWS / 128);   // 8 x 32
    gemm_tc<<<gproj, 256>>>(rq, wq_, nullptr, nullptr, 0);   // idx 1
    gemm_tc<<<gproj, 256>>>(rk, wk_, nullptr, nullptr, 1);   // idx 2
    gemm_tc<<<gproj, 256>>>(rv, wv_, nullptr, nullptr, 2);   // idx 3

    dim3 gattn(Sn / 64, Bn * Hn);          // 32 x 32
    attn_a<<<gattn, 256, A_SMEM>>>(bias_table);              // idx 4
    if (has_attn)
        attn_b<<<gattn, 256, B_SMEM>>>(bias_table, attn);    // idx 5 (profiled)

    gemm_tc<<<gproj, 256>>>(gctx, wo_, bo, out, 3);
}

// round 11
// speedup vs baseline: 2.9581x; 1.0225x over previous
#include <cuda_runtime.h>

#define Bn 2
#define Sn 2048
#define Dn 1024
#define Hn 16
#define DKn 64
#define MAXSEQ 2048
#define MROWS (Bn * Sn)
#define OUT_ELEMS (MROWS * Dn)
#define ATTN_ELEMS ((long long)Bn * Hn * Sn * Sn)

__device__ float g_Q[Bn * Sn * Dn];
__device__ float g_K[Bn * Sn * Dn];
__device__ float g_V[Bn * Sn * Dn];
__device__ float g_CTX[Bn * Sn * Dn];
__device__ float g_RINV[Bn * Hn * Sn];
// pre-rounded (tf32-valued fp32) copies of inputs
__device__ float g_RQ[Bn * Sn * Dn];
__device__ float g_RK[Bn * Sn * Dn];
__device__ float g_RV[Bn * Sn * Dn];
__device__ float g_WQ[Dn * Dn];
__device__ float g_WK[Dn * Dn];
__device__ float g_WV[Dn * Dn];
__device__ float g_WO[Dn * Dn];

__device__ __forceinline__ unsigned f2tf(float x) {
    unsigned u;
    asm("cvt.rna.tf32.f32 %0, %1;" : "=r"(u) : "f"(x));
    return u;
}

__device__ __forceinline__ void mma_tf32(float c[4], const unsigned a[4],
                                         unsigned b0, unsigned b1) {
    asm volatile(
        "mma.sync.aligned.m16n8k8.row.col.f32.tf32.tf32.f32 "
        "{%0,%1,%2,%3}, {%4,%5,%6,%7}, {%8,%9}, {%0,%1,%2,%3};"
        : "+f"(c[0]), "+f"(c[1]), "+f"(c[2]), "+f"(c[3])
        : "r"(a[0]), "r"(a[1]), "r"(a[2]), "r"(a[3]), "r"(b0), "r"(b1));
}

__device__ __forceinline__ void cp_async16(void* dst, const void* src) {
    unsigned s = (unsigned)__cvta_generic_to_shared(dst);
    asm volatile("cp.async.cg.shared.global [%0], [%1], 16;" :: "r"(s), "l"(src));
}
__device__ __forceinline__ void cp_async4(void* dst, const void* src) {
    unsigned s = (unsigned)__cvta_generic_to_shared(dst);
    asm volatile("cp.async.ca.shared.global [%0], [%1], 4;" :: "r"(s), "l"(src));
}
__device__ __forceinline__ void cp_commit() {
    asm volatile("cp.async.commit_group;");
}
template <int N>
__device__ __forceinline__ void cp_wait() {
    asm volatile("cp.async.wait_group %0;" :: "n"(N));
}

// ---------------------------------------------------------------------------
// Fused tf32 pre-rounding of all 7 inputs (single launch).
// ---------------------------------------------------------------------------
#define N4A ((Bn * Sn * Dn) / 4)   // 1,048,576
#define N4W ((Dn * Dn) / 4)        // 262,144

__global__ __launch_bounds__(256)
void round_all(const float* __restrict__ q, const float* __restrict__ k,
               const float* __restrict__ v, const float* __restrict__ wq,
               const float* __restrict__ wk, const float* __restrict__ wv,
               const float* __restrict__ wo)
{
    int i = blockIdx.x * 256 + threadIdx.x;
    const float* s;
    float* d;
    int j = i;
    if (j < N4A)                 { s = q;  d = g_RQ; }
    else if ((j -= N4A) < N4A)   { s = k;  d = g_RK; }
    else if ((j -= N4A) < N4A)   { s = v;  d = g_RV; }
    else if ((j -= N4A) < N4W)   { s = wq; d = g_WQ; }
    else if ((j -= N4W) < N4W)   { s = wk; d = g_WK; }
    else if ((j -= N4W) < N4W)   { s = wv; d = g_WV; }
    else                         { j -= N4W; s = wo; d = g_WO; }
    float4 x = ((const float4*)s)[j];
    x.x = __uint_as_float(f2tf(x.x));
    x.y = __uint_as_float(f2tf(x.y));
    x.z = __uint_as_float(f2tf(x.z));
    x.w = __uint_as_float(f2tf(x.w));
    ((float4*)d)[j] = x;
}

// ---------------------------------------------------------------------------
// Projection GEMM, 3-stage cp.async pipeline (BK=16, prefetch depth 2).
// mode 4: fused QKV — blockIdx.z selects (g_RQ,g_WQ,g_Q)/(K)/(V), permuted store.
// mode 3: A/W passed in, C = d_out + bias, plain store.
// ---------------------------------------------------------------------------
#define GP 20
#define GSTG 3
#define GTILE (128 * GP)
#define GEMM_SMEM (2 * GSTG * GTILE * 4)   // 61,440 B -> dynamic smem

__global__ __launch_bounds__(256)
void gemm_tc(const float* __restrict__ Ain, const float* __restrict__ Win,
             const float* __restrict__ bias, float* __restrict__ Cext, int mode)
{
    extern __shared__ float gsm[];
    float* As = gsm;                  // [GSTG][GTILE]
    float* Ws = gsm + GSTG * GTILE;   // [GSTG][GTILE]

    const float* A;
    const float* W;
    float* C;
    if (mode == 4) {
        int z = blockIdx.z;
        A = (z == 0) ? g_RQ : (z == 1) ? g_RK : g_RV;
        W = (z == 0) ? g_WQ : (z == 1) ? g_WK : g_WV;
        C = (z == 0) ? g_Q  : (z == 1) ? g_K  : g_V;
    } else {
        A = Ain; W = Win; C = Cext;
    }

    const int tid = threadIdx.x;
    const int w = tid >> 5, lane = tid & 31, g = lane >> 2, qr = lane & 3;
    const int wm = w >> 2, wn = w & 3;
    const int m0 = blockIdx.y * 128, n0 = blockIdx.x * 128;
    const int row_f = tid >> 2, c4 = tid & 3;

    float c[4][4][4] = {};

    // Prologue: prefetch tiles 0 and 1
#pragma unroll
    for (int p = 0; p < 2; p++) {
#pragma unroll
        for (int it = 0; it < 2; it++) {
            int rr = row_f + it * 64;
            cp_async16(&As[p * GTILE + rr * GP + c4 * 4],
                       &A[(size_t)(m0 + rr) * 1024 + p * 16 + c4 * 4]);
            cp_async16(&Ws[p * GTILE + rr * GP + c4 * 4],
                       &W[(size_t)(n0 + rr) * 1024 + p * 16 + c4 * 4]);
        }
        cp_commit();
    }

    int st = 0, pf = 2;
    for (int i = 0; i < 64; i++) {
        if (i + 1 < 64) cp_wait<1>(); else cp_wait<0>();
        __syncthreads();

        if (i + 2 < 64) {
            int kn = (i + 2) * 16;
#pragma unroll
            for (int it = 0; it < 2; it++) {
                int rr = row_f + it * 64;
                cp_async16(&As[pf * GTILE + rr * GP + c4 * 4],
                           &A[(size_t)(m0 + rr) * 1024 + kn + c4 * 4]);
                cp_async16(&Ws[pf * GTILE + rr * GP + c4 * 4],
                           &W[(size_t)(n0 + rr) * 1024 + kn + c4 * 4]);
            }
            cp_commit();
        }

        const float* At = As + st * GTILE;
        const float* Wt = Ws + st * GTILE;
#pragma unroll
        for (int kk = 0; kk < 16; kk += 8) {
            unsigned a[4][4], b[4][2];
#pragma unroll
            for (int mi = 0; mi < 4; mi++) {
                int r = wm * 64 + mi * 16 + g;
                a[mi][0] = __float_as_uint(At[r * GP + kk + qr]);
                a[mi][1] = __float_as_uint(At[(r + 8) * GP + kk + qr]);
                a[mi][2] = __float_as_uint(At[r * GP + kk + qr + 4]);
                a[mi][3] = __float_as_uint(At[(r + 8) * GP + kk + qr + 4]);
            }
#pragma unroll
            for (int ni = 0; ni < 4; ni++) {
                int col = wn * 32 + ni * 8 + g;
                b[ni][0] = __float_as_uint(Wt[col * GP + kk + qr]);
                b[ni][1] = __float_as_uint(Wt[col * GP + kk + qr + 4]);
            }
#pragma unroll
            for (int mi = 0; mi < 4; mi++)
#pragma unroll
                for (int ni = 0; ni < 4; ni++)
                    mma_tf32(c[mi][ni], a[mi], b[ni][0], b[ni][1]);
        }

        st = (st + 1 == GSTG) ? 0 : st + 1;
        pf = (pf + 1 == GSTG) ? 0 : pf + 1;
    }

#pragma unroll
    for (int mi = 0; mi < 4; mi++)
#pragma unroll
        for (int ni = 0; ni < 4; ni++)
#pragma unroll
            for (int half = 0; half < 2; half++) {
                int row = m0 + wm * 64 + mi * 16 + g + half * 8;
                int col = n0 + wn * 32 + ni * 8 + 2 * qr;
                float v0 = c[mi][ni][half * 2 + 0];
                float v1 = c[mi][ni][half * 2 + 1];
                if (mode == 3) {
                    v0 += bias[col];
                    v1 += bias[col + 1];
                    *(float2*)&C[(size_t)row * 1024 + col] = make_float2(v0, v1);
                } else {
                    v0 = __uint_as_float(f2tf(v0));
                    v1 = __uint_as_float(f2tf(v1));
                    int b_ = row >> 11, s_ = row & (Sn - 1);
                    int h_ = col >> 6, dk = col & 63;
                    size_t o = (((size_t)(b_ * Hn + h_) * Sn) + s_) * DKn + dk;
                    *(float2*)&C[o] = make_float2(v0, v1);
                }
            }
}

// ---------------------------------------------------------------------------
// attn_a: ctx + rowsums only (unchanged from R10).
// ---------------------------------------------------------------------------
#define KROW 68
#define VROW 72
#define KTILE (64 * KROW)
#define VTILE (64 * VROW)
#define A_SMEM ((2 * KTILE + 2 * VTILE) * 4)
#define B_SMEM ((2 * KTILE) * 4)

__global__ __launch_bounds__(256)
void attn_a(const float* __restrict__ bias_table)
{
    extern __shared__ float sm[];
    float* KsF = sm;                 // [2][KTILE]
    float* VsF = sm + 2 * KTILE;     // [2][VTILE]
    __shared__ float bias_s[2][128];
    __shared__ float rs[2][64];
    __shared__ float rinv_s[64];

    const int tid = threadIdx.x;
    const int w = tid >> 5, lane = tid & 31, g = lane >> 2, qr = lane & 3;
    const int wq = w >> 1, wk = w & 1;
    const int qt = blockIdx.x, bh = blockIdx.y;
    const int b_ = bh >> 4, h_ = bh & 15;
    const int q0 = qt * 64;
    const int qlo = wq * 16 + g;

    const float* Qb = g_Q + (size_t)bh * Sn * DKn;
    const float* Kb = g_K + (size_t)bh * Sn * DKn;
    const float* Vb = g_V + (size_t)bh * Sn * DKn;
    const float* bias_base = bias_table + (size_t)(q0 + MAXSEQ - 1 - 63) * Hn + h_;

    unsigned qa[8][4];
    {
        const float* r0 = Qb + (size_t)(q0 + qlo) * DKn;
        const float* r1 = r0 + 8 * DKn;
#pragma unroll
        for (int kc = 0; kc < 8; kc++) {
            qa[kc][0] = __float_as_uint(r0[kc * 8 + qr]);
            qa[kc][1] = __float_as_uint(r1[kc * 8 + qr]);
            qa[kc][2] = __float_as_uint(r0[kc * 8 + qr + 4]);
            qa[kc][3] = __float_as_uint(r1[kc * 8 + qr + 4]);
        }
    }

    const int src0 = (lane & 28) | (qr >> 1);
    const int src1 = src0 + 2;
    const bool odd = (qr & 1);

    float ctx[8][4] = {};
    float psum[2] = {};

    {
#pragma unroll
        for (int it = 0; it < 4; it++) {
            int idx = tid + it * 256;
            int row = idx >> 4, cc = idx & 15;
            cp_async16(&KsF[row * KROW + cc * 4], &Kb[(size_t)row * DKn + cc * 4]);
            cp_async16(&VsF[row * VROW + cc * 4], &Vb[(size_t)row * DKn + cc * 4]);
        }
        if (tid < 127) cp_async4(&bias_s[0][tid], bias_base + (size_t)tid * Hn);
        cp_commit();
    }

    for (int kt = 0; kt < 32; kt++) {
        const int st = kt & 1;
        cp_wait<0>();
        __syncthreads();

        if (kt + 1 < 32) {
            const int k1 = (kt + 1) * 64;
            const float* Kn = Kb + (size_t)k1 * DKn;
            const float* Vn = Vb + (size_t)k1 * DKn;
            float* Kd = KsF + (st ^ 1) * KTILE;
            float* Vd = VsF + (st ^ 1) * VTILE;
#pragma unroll
            for (int it = 0; it < 4; it++) {
                int idx = tid + it * 256;
                int row = idx >> 4, cc = idx & 15;
                cp_async16(&Kd[row * KROW + cc * 4], &Kn[(size_t)row * DKn + cc * 4]);
                cp_async16(&Vd[row * VROW + cc * 4], &Vn[(size_t)row * DKn + cc * 4]);
            }
            if (tid < 127)
                cp_async4(&bias_s[st ^ 1][tid], bias_base + (size_t)(tid - k1) * Hn);
            cp_commit();
        }

        const float* Kt = KsF + st * KTILE;
        const float* Vt = VsF + st * VTILE;

        float sacc[4][4] = {};
#pragma unroll
        for (int kc = 0; kc < 8; kc++) {
#pragma unroll
            for (int ni = 0; ni < 4; ni++) {
                int col = wk * 32 + ni * 8 + g;
                unsigned b0 = __float_as_uint(Kt[col * KROW + kc * 8 + qr]);
                unsigned b1 = __float_as_uint(Kt[col * KROW + kc * 8 + qr + 4]);
                mma_tf32(sacc[ni], qa[kc], b0, b1);
            }
        }

        unsigned pA[4][4];
#pragma unroll
        for (int ni = 0; ni < 4; ni++) {
            int kj = wk * 32 + ni * 8 + 2 * qr;
            int idx0 = qlo - kj + 63;
            float p0 = __expf(sacc[ni][0] * 0.125f + bias_s[st][idx0]);
            float p1 = __expf(sacc[ni][1] * 0.125f + bias_s[st][idx0 - 1]);
            float p2 = __expf(sacc[ni][2] * 0.125f + bias_s[st][idx0 + 8]);
            float p3 = __expf(sacc[ni][3] * 0.125f + bias_s[st][idx0 + 7]);
            psum[0] += p0 + p1;
            psum[1] += p2 + p3;
            float u0 = __shfl_sync(0xffffffffu, p0, src0);
            float u1 = __shfl_sync(0xffffffffu, p1, src0);
            pA[ni][0] = f2tf(odd ? u1 : u0);
            float u2 = __shfl_sync(0xffffffffu, p2, src0);
            float u3 = __shfl_sync(0xffffffffu, p3, src0);
            pA[ni][1] = f2tf(odd ? u3 : u2);
            float u4 = __shfl_sync(0xffffffffu, p0, src1);
            float u5 = __shfl_sync(0xffffffffu, p1, src1);
            pA[ni][2] = f2tf(odd ? u5 : u4);
            float u6 = __shfl_sync(0xffffffffu, p2, src1);
            float u7 = __shfl_sync(0xffffffffu, p3, src1);
            pA[ni][3] = f2tf(odd ? u7 : u6);
        }

#pragma unroll
        for (int kc2 = 0; kc2 < 4; kc2++) {
            int krow = wk * 32 + kc2 * 8 + qr;
#pragma unroll
            for (int n2 = 0; n2 < 8; n2++) {
                unsigned b0 = __float_as_uint(Vt[krow * VROW + n2 * 8 + g]);
                unsigned b1 = __float_as_uint(Vt[(krow + 4) * VROW + n2 * 8 + g]);
                mma_tf32(ctx[n2], pA[kc2], b0, b1);
            }
        }
    }

#pragma unroll
    for (int h2 = 0; h2 < 2; h2++) {
        float v = psum[h2];
        v += __shfl_xor_sync(0xffffffffu, v, 1);
        v += __shfl_xor_sync(0xffffffffu, v, 2);
        if (qr == 0) rs[wk][wq * 16 + h2 * 8 + g] = v;
    }
    __syncthreads();

    float* Kf = KsF;
    if (wk == 1) {
#pragma unroll
        for (int n2 = 0; n2 < 8; n2++) {
            *(float2*)&Kf[qlo * KROW + n2 * 8 + 2 * qr] =
                make_float2(ctx[n2][0], ctx[n2][1]);
            *(float2*)&Kf[(qlo + 8) * KROW + n2 * 8 + 2 * qr] =
                make_float2(ctx[n2][2], ctx[n2][3]);
        }
    }
    if (tid < 64) {
        float r = 1.0f / (rs[0][tid] + rs[1][tid]);
        rinv_s[tid] = r;
        g_RINV[(size_t)bh * Sn + q0 + tid] = r;
    }
    __syncthreads();

    if (wk == 0) {
        float r0 = rinv_s[qlo], r1 = rinv_s[qlo + 8];
#pragma unroll
        for (int n2 = 0; n2 < 8; n2++) {
            float2 o0 = *(float2*)&Kf[qlo * KROW + n2 * 8 + 2 * qr];
            float2 o1 = *(float2*)&Kf[(qlo + 8) * KROW + n2 * 8 + 2 * qr];
            int col = h_ * 64 + n2 * 8 + 2 * qr;
            size_t a0 = ((size_t)(b_ * Sn + q0 + qlo)) * Dn + col;
            *(float2*)&g_CTX[a0] = make_float2(
                __uint_as_float(f2tf((ctx[n2][0] + o0.x) * r0)),
                __uint_as_float(f2tf((ctx[n2][1] + o0.y) * r0)));
            *(float2*)&g_CTX[a0 + 8 * Dn] = make_float2(
                __uint_as_float(f2tf((ctx[n2][2] + o1.x) * r1)),
                __uint_as_float(f2tf((ctx[n2][3] + o1.y) * r1)));
        }
    }
}

// ---------------------------------------------------------------------------
// attn_b: recompute S, write normalized attn (unchanged from R10).
// ---------------------------------------------------------------------------
__global__ __launch_bounds__(256)
void attn_b(const float* __restrict__ bias_table, float* __restrict__ attn_out)
{
    extern __shared__ float sm[];
    float* KsF = sm;                 // [2][KTILE]
    __shared__ float bias_s[2][128];

    const int tid = threadIdx.x;
    const int w = tid >> 5, lane = tid & 31, g = lane >> 2, qr = lane & 3;
    const int wq = w >> 1, wk = w & 1;
    const int qt = blockIdx.x, bh = blockIdx.y;
    const int h_ = bh & 15;
    const int q0 = qt * 64;
    const int qlo = wq * 16 + g;

    const float* Qb = g_Q + (size_t)bh * Sn * DKn;
    const float* Kb = g_K + (size_t)bh * Sn * DKn;
    const float* bias_base = bias_table + (size_t)(q0 + MAXSEQ - 1 - 63) * Hn + h_;

    unsigned qa[8][4];
    {
        const float* r0 = Qb + (size_t)(q0 + qlo) * DKn;
        const float* r1 = r0 + 8 * DKn;
#pragma unroll
        for (int kc = 0; kc < 8; kc++) {
            qa[kc][0] = __float_as_uint(r0[kc * 8 + qr]);
            qa[kc][1] = __float_as_uint(r1[kc * 8 + qr]);
            qa[kc][2] = __float_as_uint(r0[kc * 8 + qr + 4]);
            qa[kc][3] = __float_as_uint(r1[kc * 8 + qr + 4]);
        }
    }

    const float rv0 = g_RINV[(size_t)bh * Sn + q0 + qlo];
    const float rv1 = g_RINV[(size_t)bh * Sn + q0 + qlo + 8];

    {
#pragma unroll
        for (int it = 0; it < 4; it++) {
            int idx = tid + it * 256;
            int row = idx >> 4, cc = idx & 15;
            cp_async16(&KsF[row * KROW + cc * 4], &Kb[(size_t)row * DKn + cc * 4]);
        }
        if (tid < 127) cp_async4(&bias_s[0][tid], bias_base + (size_t)tid * Hn);
        cp_commit();
    }

    for (int kt = 0; kt < 32; kt++) {
        const int st = kt & 1;
        const int k0 = kt * 64;
        cp_wait<0>();
        __syncthreads();

        if (kt + 1 < 32) {
            const int k1 = (kt + 1) * 64;
            const float* Kn = Kb + (size_t)k1 * DKn;
            float* Kd = KsF + (st ^ 1) * KTILE;
#pragma unroll
            for (int it = 0; it < 4; it++) {
                int idx = tid + it * 256;
                int row = idx >> 4, cc = idx & 15;
                cp_async16(&Kd[row * KROW + cc * 4], &Kn[(size_t)row * DKn + cc * 4]);
            }
            if (tid < 127)
                cp_async4(&bias_s[st ^ 1][tid], bias_base + (size_t)(tid - k1) * Hn);
            cp_commit();
        }

        const float* Kt = KsF + st * KTILE;

        float sacc[4][4] = {};
#pragma unroll
        for (int kc = 0; kc < 8; kc++) {
#pragma unroll
            for (int ni = 0; ni < 4; ni++) {
                int col = wk * 32 + ni * 8 + g;
                unsigned b0 = __float_as_uint(Kt[col * KROW + kc * 8 + qr]);
                unsigned b1 = __float_as_uint(Kt[col * KROW + kc * 8 + qr + 4]);
                mma_tf32(sacc[ni], qa[kc], b0, b1);
            }
        }

        size_t rbase0 = ((size_t)(bh * Sn + q0 + qlo)) * Sn + k0;
        size_t rbase1 = rbase0 + 8 * (size_t)Sn;
#pragma unroll
        for (int ni = 0; ni < 4; ni++) {
            int kj = wk * 32 + ni * 8 + 2 * qr;
            int idx0 = qlo - kj + 63;
            float p0 = __expf(sacc[ni][0] * 0.125f + bias_s[st][idx0]) * rv0;
            float p1 = __expf(sacc[ni][1] * 0.125f + bias_s[st][idx0 - 1]) * rv0;
            float p2 = __expf(sacc[ni][2] * 0.125f + bias_s[st][idx0 + 8]) * rv1;
            float p3 = __expf(sacc[ni][3] * 0.125f + bias_s[st][idx0 + 7]) * rv1;
            *(float2*)&attn_out[rbase0 + kj] = make_float2(p0, p1);
            *(float2*)&attn_out[rbase1 + kj] = make_float2(p2, p3);
        }
    }
}

// ---------------------------------------------------------------------------
extern "C" void kernel_launch(void* const* d_in, const int* in_sizes, int n_in,
                              void* d_out, int out_size)
{
    const float* query      = (const float*)d_in[0];
    const float* key        = (const float*)d_in[1];
    const float* value      = (const float*)d_in[2];
    const float* Wq         = (const float*)d_in[3];
    const float* Wk         = (const float*)d_in[4];
    const float* Wv         = (const float*)d_in[5];
    const float* Wo         = (const float*)d_in[6];
    const float* bo         = (const float*)d_in[7];
    const float* bias_table = (const float*)d_in[8];

    float* out = (float*)d_out;
    const bool has_attn = (long long)out_size >= (OUT_ELEMS + ATTN_ELEMS);
    float* attn = has_attn ? out + OUT_ELEMS : nullptr;

    cudaFuncSetAttribute(gemm_tc, cudaFuncAttributeMaxDynamicSharedMemorySize, GEMM_SMEM);
    cudaFuncSetAttribute(attn_a, cudaFuncAttributeMaxDynamicSharedMemorySize, A_SMEM);
    cudaFuncSetAttribute(attn_b, cudaFuncAttributeMaxDynamicSharedMemorySize, B_SMEM);

    float *gctx;
    cudaGetSymbolAddress((void**)&gctx, g_CTX);
    float *wo_;
    cudaGetSymbolAddress((void**)&wo_, g_WO);

    const int total4 = 3 * N4A + 4 * N4W;            // 4,194,304
    round_all<<<total4 / 256, 256>>>(query, key, value, Wq, Wk, Wv, Wo);

    dim3 gqkv(1024 / 128, MROWS / 128, 3);           // 8 x 32 x 3, fused QKV
    gemm_tc<<<gqkv, 256, GEMM_SMEM>>>(nullptr, nullptr, nullptr, nullptr, 4);

    dim3 gattn(Sn / 64, Bn * Hn);                    // 32 x 32
    attn_a<<<gattn, 256, A_SMEM>>>(bias_table);
    if (has_attn)
        attn_b<<<gattn, 256, B_SMEM>>>(bias_table, attn);

    dim3 gproj(1024 / 128, MROWS / 128);             // 8 x 32
    gemm_tc<<<gproj, 256, GEMM_SMEM>>>(gctx, wo_, bo, out, 3);
}

// round 12
// speedup vs baseline: 3.0286x; 1.0238x over previous
#include <cuda_runtime.h>

#define Bn 2
#define Sn 2048
#define Dn 1024
#define Hn 16
#define DKn 64
#define MAXSEQ 2048
#define MROWS (Bn * Sn)
#define OUT_ELEMS (MROWS * Dn)
#define ATTN_ELEMS ((long long)Bn * Hn * Sn * Sn)

__device__ float g_Q[Bn * Sn * Dn];
__device__ float g_K[Bn * Sn * Dn];
__device__ float g_V[Bn * Sn * Dn];
__device__ float g_CTX[Bn * Sn * Dn];
__device__ float g_RINV[Bn * Hn * Sn];
// pre-rounded (tf32-valued fp32) copies of inputs
__device__ float g_RQ[Bn * Sn * Dn];
__device__ float g_RK[Bn * Sn * Dn];
__device__ float g_RV[Bn * Sn * Dn];
__device__ float g_WQ[Dn * Dn];
__device__ float g_WK[Dn * Dn];
__device__ float g_WV[Dn * Dn];
__device__ float g_WO[Dn * Dn];

__device__ __forceinline__ unsigned f2tf(float x) {
    unsigned u;
    asm("cvt.rna.tf32.f32 %0, %1;" : "=r"(u) : "f"(x));
    return u;
}

__device__ __forceinline__ void mma_tf32(float c[4], const unsigned a[4],
                                         unsigned b0, unsigned b1) {
    asm volatile(
        "mma.sync.aligned.m16n8k8.row.col.f32.tf32.tf32.f32 "
        "{%0,%1,%2,%3}, {%4,%5,%6,%7}, {%8,%9}, {%0,%1,%2,%3};"
        : "+f"(c[0]), "+f"(c[1]), "+f"(c[2]), "+f"(c[3])
        : "r"(a[0]), "r"(a[1]), "r"(a[2]), "r"(a[3]), "r"(b0), "r"(b1));
}

__device__ __forceinline__ void cp_async16(void* dst, const void* src) {
    unsigned s = (unsigned)__cvta_generic_to_shared(dst);
    asm volatile("cp.async.cg.shared.global [%0], [%1], 16;" :: "r"(s), "l"(src));
}
__device__ __forceinline__ void cp_async4(void* dst, const void* src) {
    unsigned s = (unsigned)__cvta_generic_to_shared(dst);
    asm volatile("cp.async.ca.shared.global [%0], [%1], 4;" :: "r"(s), "l"(src));
}
__device__ __forceinline__ void cp_commit() {
    asm volatile("cp.async.commit_group;");
}
template <int N>
__device__ __forceinline__ void cp_wait() {
    asm volatile("cp.async.wait_group %0;" :: "n"(N));
}

// ---------------------------------------------------------------------------
// Fused tf32 pre-rounding of all 7 inputs (single launch).
// ---------------------------------------------------------------------------
#define N4A ((Bn * Sn * Dn) / 4)   // 1,048,576
#define N4W ((Dn * Dn) / 4)        // 262,144

__global__ __launch_bounds__(256)
void round_all(const float* __restrict__ q, const float* __restrict__ k,
               const float* __restrict__ v, const float* __restrict__ wq,
               const float* __restrict__ wk, const float* __restrict__ wv,
               const float* __restrict__ wo)
{
    int i = blockIdx.x * 256 + threadIdx.x;
    const float* s;
    float* d;
    int j = i;
    if (j < N4A)                 { s = q;  d = g_RQ; }
    else if ((j -= N4A) < N4A)   { s = k;  d = g_RK; }
    else if ((j -= N4A) < N4A)   { s = v;  d = g_RV; }
    else if ((j -= N4A) < N4W)   { s = wq; d = g_WQ; }
    else if ((j -= N4W) < N4W)   { s = wk; d = g_WK; }
    else if ((j -= N4W) < N4W)   { s = wv; d = g_WV; }
    else                         { j -= N4W; s = wo; d = g_WO; }
    float4 x = ((const float4*)s)[j];
    x.x = __uint_as_float(f2tf(x.x));
    x.y = __uint_as_float(f2tf(x.y));
    x.z = __uint_as_float(f2tf(x.z));
    x.w = __uint_as_float(f2tf(x.w));
    ((float4*)d)[j] = x;
}

// ---------------------------------------------------------------------------
// Projection GEMM, 3-stage cp.async pipeline (unchanged from R11).
// ---------------------------------------------------------------------------
#define GP 20
#define GSTG 3
#define GTILE (128 * GP)
#define GEMM_SMEM (2 * GSTG * GTILE * 4)

__global__ __launch_bounds__(256)
void gemm_tc(const float* __restrict__ Ain, const float* __restrict__ Win,
             const float* __restrict__ bias, float* __restrict__ Cext, int mode)
{
    extern __shared__ float gsm[];
    float* As = gsm;
    float* Ws = gsm + GSTG * GTILE;

    const float* A;
    const float* W;
    float* C;
    if (mode == 4) {
        int z = blockIdx.z;
        A = (z == 0) ? g_RQ : (z == 1) ? g_RK : g_RV;
        W = (z == 0) ? g_WQ : (z == 1) ? g_WK : g_WV;
        C = (z == 0) ? g_Q  : (z == 1) ? g_K  : g_V;
    } else {
        A = Ain; W = Win; C = Cext;
    }

    const int tid = threadIdx.x;
    const int w = tid >> 5, lane = tid & 31, g = lane >> 2, qr = lane & 3;
    const int wm = w >> 2, wn = w & 3;
    const int m0 = blockIdx.y * 128, n0 = blockIdx.x * 128;
    const int row_f = tid >> 2, c4 = tid & 3;

    float c[4][4][4] = {};

#pragma unroll
    for (int p = 0; p < 2; p++) {
#pragma unroll
        for (int it = 0; it < 2; it++) {
            int rr = row_f + it * 64;
            cp_async16(&As[p * GTILE + rr * GP + c4 * 4],
                       &A[(size_t)(m0 + rr) * 1024 + p * 16 + c4 * 4]);
            cp_async16(&Ws[p * GTILE + rr * GP + c4 * 4],
                       &W[(size_t)(n0 + rr) * 1024 + p * 16 + c4 * 4]);
        }
        cp_commit();
    }

    int st = 0, pf = 2;
    for (int i = 0; i < 64; i++) {
        if (i + 1 < 64) cp_wait<1>(); else cp_wait<0>();
        __syncthreads();

        if (i + 2 < 64) {
            int kn = (i + 2) * 16;
#pragma unroll
            for (int it = 0; it < 2; it++) {
                int rr = row_f + it * 64;
                cp_async16(&As[pf * GTILE + rr * GP + c4 * 4],
                           &A[(size_t)(m0 + rr) * 1024 + kn + c4 * 4]);
                cp_async16(&Ws[pf * GTILE + rr * GP + c4 * 4],
                           &W[(size_t)(n0 + rr) * 1024 + kn + c4 * 4]);
            }
            cp_commit();
        }

        const float* At = As + st * GTILE;
        const float* Wt = Ws + st * GTILE;
#pragma unroll
        for (int kk = 0; kk < 16; kk += 8) {
            unsigned a[4][4], b[4][2];
#pragma unroll
            for (int mi = 0; mi < 4; mi++) {
                int r = wm * 64 + mi * 16 + g;
                a[mi][0] = __float_as_uint(At[r * GP + kk + qr]);
                a[mi][1] = __float_as_uint(At[(r + 8) * GP + kk + qr]);
                a[mi][2] = __float_as_uint(At[r * GP + kk + qr + 4]);
                a[mi][3] = __float_as_uint(At[(r + 8) * GP + kk + qr + 4]);
            }
#pragma unroll
            for (int ni = 0; ni < 4; ni++) {
                int col = wn * 32 + ni * 8 + g;
                b[ni][0] = __float_as_uint(Wt[col * GP + kk + qr]);
                b[ni][1] = __float_as_uint(Wt[col * GP + kk + qr + 4]);
            }
#pragma unroll
            for (int mi = 0; mi < 4; mi++)
#pragma unroll
                for (int ni = 0; ni < 4; ni++)
                    mma_tf32(c[mi][ni], a[mi], b[ni][0], b[ni][1]);
        }

        st = (st + 1 == GSTG) ? 0 : st + 1;
        pf = (pf + 1 == GSTG) ? 0 : pf + 1;
    }

#pragma unroll
    for (int mi = 0; mi < 4; mi++)
#pragma unroll
        for (int ni = 0; ni < 4; ni++)
#pragma unroll
            for (int half = 0; half < 2; half++) {
                int row = m0 + wm * 64 + mi * 16 + g + half * 8;
                int col = n0 + wn * 32 + ni * 8 + 2 * qr;
                float v0 = c[mi][ni][half * 2 + 0];
                float v1 = c[mi][ni][half * 2 + 1];
                if (mode == 3) {
                    v0 += bias[col];
                    v1 += bias[col + 1];
                    *(float2*)&C[(size_t)row * 1024 + col] = make_float2(v0, v1);
                } else {
                    v0 = __uint_as_float(f2tf(v0));
                    v1 = __uint_as_float(f2tf(v1));
                    int b_ = row >> 11, s_ = row & (Sn - 1);
                    int h_ = col >> 6, dk = col & 63;
                    size_t o = (((size_t)(b_ * Hn + h_) * Sn) + s_) * DKn + dk;
                    *(float2*)&C[o] = make_float2(v0, v1);
                }
            }
}

// ---------------------------------------------------------------------------
// attn_a: ctx + rowsums only (unchanged from R11).
// ---------------------------------------------------------------------------
#define KROW 68
#define VROW 72
#define KTILE (64 * KROW)
#define VTILE (64 * VROW)
#define A_SMEM ((2 * KTILE + 2 * VTILE) * 4)
#define B_SMEM ((2 * KTILE) * 4)

__global__ __launch_bounds__(256)
void attn_a(const float* __restrict__ bias_table)
{
    extern __shared__ float sm[];
    float* KsF = sm;
    float* VsF = sm + 2 * KTILE;
    __shared__ float bias_s[2][128];
    __shared__ float rs[2][64];
    __shared__ float rinv_s[64];

    const int tid = threadIdx.x;
    const int w = tid >> 5, lane = tid & 31, g = lane >> 2, qr = lane & 3;
    const int wq = w >> 1, wk = w & 1;
    const int qt = blockIdx.x, bh = blockIdx.y;
    const int b_ = bh >> 4, h_ = bh & 15;
    const int q0 = qt * 64;
    const int qlo = wq * 16 + g;

    const float* Qb = g_Q + (size_t)bh * Sn * DKn;
    const float* Kb = g_K + (size_t)bh * Sn * DKn;
    const float* Vb = g_V + (size_t)bh * Sn * DKn;
    const float* bias_base = bias_table + (size_t)(q0 + MAXSEQ - 1 - 63) * Hn + h_;

    unsigned qa[8][4];
    {
        const float* r0 = Qb + (size_t)(q0 + qlo) * DKn;
        const float* r1 = r0 + 8 * DKn;
#pragma unroll
        for (int kc = 0; kc < 8; kc++) {
            qa[kc][0] = __float_as_uint(r0[kc * 8 + qr]);
            qa[kc][1] = __float_as_uint(r1[kc * 8 + qr]);
            qa[kc][2] = __float_as_uint(r0[kc * 8 + qr + 4]);
            qa[kc][3] = __float_as_uint(r1[kc * 8 + qr + 4]);
        }
    }

    const int src0 = (lane & 28) | (qr >> 1);
    const int src1 = src0 + 2;
    const bool odd = (qr & 1);

    float ctx[8][4] = {};
    float psum[2] = {};

    {
#pragma unroll
        for (int it = 0; it < 4; it++) {
            int idx = tid + it * 256;
            int row = idx >> 4, cc = idx & 15;
            cp_async16(&KsF[row * KROW + cc * 4], &Kb[(size_t)row * DKn + cc * 4]);
            cp_async16(&VsF[row * VROW + cc * 4], &Vb[(size_t)row * DKn + cc * 4]);
        }
        if (tid < 127) cp_async4(&bias_s[0][tid], bias_base + (size_t)tid * Hn);
        cp_commit();
    }

    for (int kt = 0; kt < 32; kt++) {
        const int st = kt & 1;
        cp_wait<0>();
        __syncthreads();

        if (kt + 1 < 32) {
            const int k1 = (kt + 1) * 64;
            const float* Kn = Kb + (size_t)k1 * DKn;
            const float* Vn = Vb + (size_t)k1 * DKn;
            float* Kd = KsF + (st ^ 1) * KTILE;
            float* Vd = VsF + (st ^ 1) * VTILE;
#pragma unroll
            for (int it = 0; it < 4; it++) {
                int idx = tid + it * 256;
                int row = idx >> 4, cc = idx & 15;
                cp_async16(&Kd[row * KROW + cc * 4], &Kn[(size_t)row * DKn + cc * 4]);
                cp_async16(&Vd[row * VROW + cc * 4], &Vn[(size_t)row * DKn + cc * 4]);
            }
            if (tid < 127)
                cp_async4(&bias_s[st ^ 1][tid], bias_base + (size_t)(tid - k1) * Hn);
            cp_commit();
        }

        const float* Kt = KsF + st * KTILE;
        const float* Vt = VsF + st * VTILE;

        float sacc[4][4] = {};
#pragma unroll
        for (int kc = 0; kc < 8; kc++) {
#pragma unroll
            for (int ni = 0; ni < 4; ni++) {
                int col = wk * 32 + ni * 8 + g;
                unsigned b0 = __float_as_uint(Kt[col * KROW + kc * 8 + qr]);
                unsigned b1 = __float_as_uint(Kt[col * KROW + kc * 8 + qr + 4]);
                mma_tf32(sacc[ni], qa[kc], b0, b1);
            }
        }

        unsigned pA[4][4];
#pragma unroll
        for (int ni = 0; ni < 4; ni++) {
            int kj = wk * 32 + ni * 8 + 2 * qr;
            int idx0 = qlo - kj + 63;
            float p0 = __expf(sacc[ni][0] * 0.125f + bias_s[st][idx0]);
            float p1 = __expf(sacc[ni][1] * 0.125f + bias_s[st][idx0 - 1]);
            float p2 = __expf(sacc[ni][2] * 0.125f + bias_s[st][idx0 + 8]);
            float p3 = __expf(sacc[ni][3] * 0.125f + bias_s[st][idx0 + 7]);
            psum[0] += p0 + p1;
            psum[1] += p2 + p3;
            float u0 = __shfl_sync(0xffffffffu, p0, src0);
            float u1 = __shfl_sync(0xffffffffu, p1, src0);
            pA[ni][0] = f2tf(odd ? u1 : u0);
            float u2 = __shfl_sync(0xffffffffu, p2, src0);
            float u3 = __shfl_sync(0xffffffffu, p3, src0);
            pA[ni][1] = f2tf(odd ? u3 : u2);
            float u4 = __shfl_sync(0xffffffffu, p0, src1);
            float u5 = __shfl_sync(0xffffffffu, p1, src1);
            pA[ni][2] = f2tf(odd ? u5 : u4);
            float u6 = __shfl_sync(0xffffffffu, p2, src1);
            float u7 = __shfl_sync(0xffffffffu, p3, src1);
            pA[ni][3] = f2tf(odd ? u7 : u6);
        }

#pragma unroll
        for (int kc2 = 0; kc2 < 4; kc2++) {
            int krow = wk * 32 + kc2 * 8 + qr;
#pragma unroll
            for (int n2 = 0; n2 < 8; n2++) {
                unsigned b0 = __float_as_uint(Vt[krow * VROW + n2 * 8 + g]);
                unsigned b1 = __float_as_uint(Vt[(krow + 4) * VROW + n2 * 8 + g]);
                mma_tf32(ctx[n2], pA[kc2], b0, b1);
            }
        }
    }

#pragma unroll
    for (int h2 = 0; h2 < 2; h2++) {
        float v = psum[h2];
        v += __shfl_xor_sync(0xffffffffu, v, 1);
        v += __shfl_xor_sync(0xffffffffu, v, 2);
        if (qr == 0) rs[wk][wq * 16 + h2 * 8 + g] = v;
    }
    __syncthreads();

    float* Kf = KsF;
    if (wk == 1) {
#pragma unroll
        for (int n2 = 0; n2 < 8; n2++) {
            *(float2*)&Kf[qlo * KROW + n2 * 8 + 2 * qr] =
                make_float2(ctx[n2][0], ctx[n2][1]);
            *(float2*)&Kf[(qlo + 8) * KROW + n2 * 8 + 2 * qr] =
                make_float2(ctx[n2][2], ctx[n2][3]);
        }
    }
    if (tid < 64) {
        float r = 1.0f / (rs[0][tid] + rs[1][tid]);
        rinv_s[tid] = r;
        g_RINV[(size_t)bh * Sn + q0 + tid] = r;
    }
    __syncthreads();

    if (wk == 0) {
        float r0 = rinv_s[qlo], r1 = rinv_s[qlo + 8];
#pragma unroll
        for (int n2 = 0; n2 < 8; n2++) {
            float2 o0 = *(float2*)&Kf[qlo * KROW + n2 * 8 + 2 * qr];
            float2 o1 = *(float2*)&Kf[(qlo + 8) * KROW + n2 * 8 + 2 * qr];
            int col = h_ * 64 + n2 * 8 + 2 * qr;
            size_t a0 = ((size_t)(b_ * Sn + q0 + qlo)) * Dn + col;
            *(float2*)&g_CTX[a0] = make_float2(
                __uint_as_float(f2tf((ctx[n2][0] + o0.x) * r0)),
                __uint_as_float(f2tf((ctx[n2][1] + o0.y) * r0)));
            *(float2*)&g_CTX[a0 + 8 * Dn] = make_float2(
                __uint_as_float(f2tf((ctx[n2][2] + o1.x) * r1)),
                __uint_as_float(f2tf((ctx[n2][3] + o1.y) * r1)));
        }
    }
}

// ---------------------------------------------------------------------------
// attn_b: recompute S, write normalized attn.
// NEW: 128 threads, 4 warps (2 wq x 2 wk), warp tile 32q x 32k — each
// K B-fragment feeds 2 mma (both mi), halving K-frag LDS per output element.
// ---------------------------------------------------------------------------
__global__ __launch_bounds__(128)
void attn_b(const float* __restrict__ bias_table, float* __restrict__ attn_out)
{
    extern __shared__ float sm[];
    float* KsF = sm;                 // [2][KTILE]
    __shared__ float bias_s[2][128];

    const int tid = threadIdx.x;
    const int w = tid >> 5, lane = tid & 31, g = lane >> 2, qr = lane & 3;
    const int wq = w >> 1, wk = w & 1;
    const int qt = blockIdx.x, bh = blockIdx.y;
    const int h_ = bh & 15;
    const int q0 = qt * 64;

    const float* Qb = g_Q + (size_t)bh * Sn * DKn;
    const float* Kb = g_K + (size_t)bh * Sn * DKn;
    const float* bias_base = bias_table + (size_t)(q0 + MAXSEQ - 1 - 63) * Hn + h_;

    // Q fragments: 32 rows per warp (2 mi x 16)
    unsigned qa[2][8][4];
    float rv[2][2];
#pragma unroll
    for (int mi = 0; mi < 2; mi++) {
        int qrow = wq * 32 + mi * 16 + g;
        const float* r0 = Qb + (size_t)(q0 + qrow) * DKn;
        const float* r1 = r0 + 8 * DKn;
#pragma unroll
        for (int kc = 0; kc < 8; kc++) {
            qa[mi][kc][0] = __float_as_uint(r0[kc * 8 + qr]);
            qa[mi][kc][1] = __float_as_uint(r1[kc * 8 + qr]);
            qa[mi][kc][2] = __float_as_uint(r0[kc * 8 + qr + 4]);
            qa[mi][kc][3] = __float_as_uint(r1[kc * 8 + qr + 4]);
        }
        rv[mi][0] = g_RINV[(size_t)bh * Sn + q0 + qrow];
        rv[mi][1] = g_RINV[(size_t)bh * Sn + q0 + qrow + 8];
    }

    // Prologue: prefetch tile 0 (128 threads: 8 iters over 1024 float4)
    {
#pragma unroll
        for (int it = 0; it < 8; it++) {
            int idx = tid + it * 128;
            int row = idx >> 4, cc = idx & 15;
            cp_async16(&KsF[row * KROW + cc * 4], &Kb[(size_t)row * DKn + cc * 4]);
        }
        if (tid < 127) cp_async4(&bias_s[0][tid], bias_base + (size_t)tid * Hn);
        cp_commit();
    }

    for (int kt = 0; kt < 32; kt++) {
        const int st = kt & 1;
        const int k0 = kt * 64;
        cp_wait<0>();
        __syncthreads();

        if (kt + 1 < 32) {
            const int k1 = (kt + 1) * 64;
            const float* Kn = Kb + (size_t)k1 * DKn;
            float* Kd = KsF + (st ^ 1) * KTILE;
#pragma unroll
            for (int it = 0; it < 8; it++) {
                int idx = tid + it * 128;
                int row = idx >> 4, cc = idx & 15;
                cp_async16(&Kd[row * KROW + cc * 4], &Kn[(size_t)row * DKn + cc * 4]);
            }
            if (tid < 127)
                cp_async4(&bias_s[st ^ 1][tid], bias_base + (size_t)(tid - k1) * Hn);
            cp_commit();
        }

        const float* Kt = KsF + st * KTILE;

        // S: 32q x 32k per warp; each b-frag feeds both mi
        float sacc[2][4][4] = {};
#pragma unroll
        for (int kc = 0; kc < 8; kc++) {
#pragma unroll
            for (int ni = 0; ni < 4; ni++) {
                int col = wk * 32 + ni * 8 + g;
                unsigned b0 = __float_as_uint(Kt[col * KROW + kc * 8 + qr]);
                unsigned b1 = __float_as_uint(Kt[col * KROW + kc * 8 + qr + 4]);
                mma_tf32(sacc[0][ni], qa[0][kc], b0, b1);
                mma_tf32(sacc[1][ni], qa[1][kc], b0, b1);
            }
        }

#pragma unroll
        for (int mi = 0; mi < 2; mi++) {
            int qi = wq * 32 + mi * 16 + g;
            size_t rbase0 = ((size_t)(bh * Sn + q0 + qi)) * Sn + k0;
            size_t rbase1 = rbase0 + 8 * (size_t)Sn;
#pragma unroll
            for (int ni = 0; ni < 4; ni++) {
                int kj = wk * 32 + ni * 8 + 2 * qr;
                int idx0 = qi - kj + 63;
                float p0 = __expf(sacc[mi][ni][0] * 0.125f + bias_s[st][idx0]) * rv[mi][0];
                float p1 = __expf(sacc[mi][ni][1] * 0.125f + bias_s[st][idx0 - 1]) * rv[mi][0];
                float p2 = __expf(sacc[mi][ni][2] * 0.125f + bias_s[st][idx0 + 8]) * rv[mi][1];
                float p3 = __expf(sacc[mi][ni][3] * 0.125f + bias_s[st][idx0 + 7]) * rv[mi][1];
                *(float2*)&attn_out[rbase0 + kj] = make_float2(p0, p1);
                *(float2*)&attn_out[rbase1 + kj] = make_float2(p2, p3);
            }
        }
    }
}

// ---------------------------------------------------------------------------
extern "C" void kernel_launch(void* const* d_in, const int* in_sizes, int n_in,
                              void* d_out, int out_size)
{
    const float* query      = (const float*)d_in[0];
    const float* key        = (const float*)d_in[1];
    const float* value      = (const float*)d_in[2];
    const float* Wq         = (const float*)d_in[3];
    const float* Wk         = (const float*)d_in[4];
    const float* Wv         = (const float*)d_in[5];
    const float* Wo         = (const float*)d_in[6];
    const float* bo         = (const float*)d_in[7];
    const float* bias_table = (const float*)d_in[8];

    float* out = (float*)d_out;
    const bool has_attn = (long long)out_size >= (OUT_ELEMS + ATTN_ELEMS);
    float* attn = has_attn ? out + OUT_ELEMS : nullptr;

    cudaFuncSetAttribute(gemm_tc, cudaFuncAttributeMaxDynamicSharedMemorySize, GEMM_SMEM);
    cudaFuncSetAttribute(attn_a, cudaFuncAttributeMaxDynamicSharedMemorySize, A_SMEM);
    cudaFuncSetAttribute(attn_b, cudaFuncAttributeMaxDynamicSharedMemorySize, B_SMEM);

    float *gctx;
    cudaGetSymbolAddress((void**)&gctx, g_CTX);
    float *wo_;
    cudaGetSymbolAddress((void**)&wo_, g_WO);

    const int total4 = 3 * N4A + 4 * N4W;            // 4,194,304
    round_all<<<total4 / 256, 256>>>(query, key, value, Wq, Wk, Wv, Wo);

    dim3 gqkv(1024 / 128, MROWS / 128, 3);           // fused QKV
    gemm_tc<<<gqkv, 256, GEMM_SMEM>>>(nullptr, nullptr, nullptr, nullptr, 4);

    dim3 gattn(Sn / 64, Bn * Hn);                    // 32 x 32
    attn_a<<<gattn, 256, A_SMEM>>>(bias_table);
    if (has_attn)
        attn_b<<<gattn, 128, B_SMEM>>>(bias_table, attn);

    dim3 gproj(1024 / 128, MROWS / 128);
    gemm_tc<<<gproj, 256, GEMM_SMEM>>>(gctx, wo_, bo, out, 3);
}